// round 14
// baseline (speedup 1.0000x reference)
#include <cuda_runtime.h>
#include <cuda_fp16.h>
#include <math.h>
#include <cstdint>

// ---------------------------------------------------------------------------
// Constants: B=16, T=512, TA=1024, NREG=4, D=512, HID=256, HEADS=4
// Region nodes: n = region*8192 + b*512 + t ; audio nodes: n = 32768 + b*1024 + ta
// ---------------------------------------------------------------------------
#define NNODES 49152

typedef __half half_t;

// Scratch (device globals)
__device__ half_t g_hh[(size_t)NNODES * 1024];    // GEMM output (fp16)
__device__ half_t g_a0[(size_t)NNODES * 1024];    // activations (ping)
__device__ half_t g_a1[(size_t)NNODES * 1024];    // activations (pong)
__device__ half_t g_wh[3014656];                  // weights fp16
__device__ float  g_pas8[NNODES * 8];
__device__ float  g_pad8[NNODES * 8];
__device__ float  g_part[16 * 256];               // per-batch accumulators

struct Ptr5 { const float* p[5]; };

// ---------------------------------------------------------------------------
// helpers
// ---------------------------------------------------------------------------
__device__ __forceinline__ uint32_t smem_u32(const void* p) {
    uint32_t a;
    asm("{ .reg .u64 t; cvta.to.shared.u64 t, %1; cvt.u32.u64 %0, t; }" : "=r"(a) : "l"(p));
    return a;
}
__device__ __forceinline__ uint32_t sw_off(int row, int c16) {
    int p = row >> 1;
    int c = ((row & 1) * 4 + c16) ^ (p & 7);
    return (uint32_t)(p * 128 + (c << 4));
}
__device__ __forceinline__ void ldsm_x4(uint32_t r[4], uint32_t addr) {
    asm volatile("ldmatrix.sync.aligned.m8n8.x4.shared.b16 {%0,%1,%2,%3}, [%4];"
                 : "=r"(r[0]), "=r"(r[1]), "=r"(r[2]), "=r"(r[3]) : "r"(addr));
}
__device__ __forceinline__ void mma_f16(float d[4], const uint32_t a[4],
                                        uint32_t b0, uint32_t b1) {
    asm volatile(
        "mma.sync.aligned.m16n8k16.row.col.f32.f16.f16.f32 "
        "{%0,%1,%2,%3}, {%4,%5,%6,%7}, {%8,%9}, {%0,%1,%2,%3};"
        : "+f"(d[0]), "+f"(d[1]), "+f"(d[2]), "+f"(d[3])
        : "r"(a[0]), "r"(a[1]), "r"(a[2]), "r"(a[3]), "r"(b0), "r"(b1));
}
__device__ __forceinline__ void cpa16(uint32_t sm, const void* g) {
    asm volatile("cp.async.cg.shared.global [%0], [%1], 16;" :: "r"(sm), "l"(g));
}
#define CP_COMMIT() asm volatile("cp.async.commit_group;" ::: "memory")

__device__ __forceinline__ float4 ld_h4(const half_t* p) {
    uint2 u = *(const uint2*)p;
    __half2 a = *reinterpret_cast<__half2*>(&u.x);
    __half2 b = *reinterpret_cast<__half2*>(&u.y);
    float2 fa = __half22float2(a), fb = __half22float2(b);
    return make_float4(fa.x, fa.y, fb.x, fb.y);
}
__device__ __forceinline__ void st_h4(half_t* P, size_t idx, float4 o) {
    __half2 h0 = __floats2half2_rn(o.x, o.y), h1 = __floats2half2_rn(o.z, o.w);
    uint2 u;
    u.x = *reinterpret_cast<uint32_t*>(&h0);
    u.y = *reinterpret_cast<uint32_t*>(&h1);
    *(uint2*)(P + idx) = u;
}
__device__ __forceinline__ uint4 pack8h(float4 a, float4 b) {
    __half2 h0 = __floats2half2_rn(a.x, a.y), h1 = __floats2half2_rn(a.z, a.w);
    __half2 h2 = __floats2half2_rn(b.x, b.y), h3 = __floats2half2_rn(b.z, b.w);
    uint4 u;
    u.x = *reinterpret_cast<uint32_t*>(&h0);
    u.y = *reinterpret_cast<uint32_t*>(&h1);
    u.z = *reinterpret_cast<uint32_t*>(&h2);
    u.w = *reinterpret_cast<uint32_t*>(&h3);
    return u;
}

// ---------------------------------------------------------------------------
// prep_w: weight transpose->fp16 (2944 blocks) + part zeroing (block 2944)
// ---------------------------------------------------------------------------
__device__ void tsp_block_h(const float* __restrict__ in, half_t* __restrict__ oh,
                            int R, int C, int gx, int gy, float (*tile)[33])
{
    int tx = threadIdx.x & 31, ty = threadIdx.x >> 5;
    int c0 = gx * 32, r0 = gy * 32;
    for (int i = ty; i < 32; i += 8)
        tile[i][tx] = in[(size_t)(r0 + i) * C + c0 + tx];
    __syncthreads();
    for (int i = ty; i < 32; i += 8)
        oh[(size_t)(c0 + i) * R + r0 + tx] = __float2half_rn(tile[tx][i]);
}

__global__ __launch_bounds__(256) void prep_w_kernel(
    Ptr5 wP, const float* __restrict__ W0, const float* __restrict__ W1,
    const float* __restrict__ W2, half_t* __restrict__ wh, float* __restrict__ part)
{
    __shared__ float tile[32][33];
    const size_t OFF_W0 = 5 * 131072;
    const size_t OFF_W1 = OFF_W0 + 262144;
    const size_t OFF_W2 = OFF_W1 + 1048576;
    int bid = blockIdx.x;
    if (bid == 2944) {
        for (int i = threadIdx.x; i < 16 * 256; i += 256) part[i] = 0.f;
        return;
    }
    if (bid < 640) {
        int i = bid >> 7, rem = bid & 127;
        tsp_block_h(wP.p[i], wh + (size_t)i * 131072, 512, 256, rem & 7, rem >> 3, tile);
    } else if (bid < 896) {
        int rem = bid - 640;
        tsp_block_h(W0, wh + OFF_W0, 256, 1024, rem & 31, rem >> 5, tile);
    } else if (bid < 1920) {
        int rem = bid - 896;
        tsp_block_h(W1, wh + OFF_W1, 1024, 1024, rem & 31, rem >> 5, tile);
    } else {
        int rem = bid - 1920;
        tsp_block_h(W2, wh + OFF_W2, 1024, 1024, rem & 31, rem >> 5, tile);
    }
}

// ---------------------------------------------------------------------------
// fp16 GEMM: C = A @ B^T (+bias), fp32 accumulate.
// CTA 128x128, 8 warps (4m x 2n), warp 32x64, K-CHUNK 64 (2x 32-sub-tiles),
// 3-stage cp.async, 2 CTAs/SM. AF32=1: A read fp32 + in-register convert.
// Fused alpha dots -> pas8/pad8.
// Stage layout: A sub0 8K | A sub1 8K | B sub0 8K | B sub1 8K = 32KB.
// ---------------------------------------------------------------------------
#define STAGE_BYTES 32768
#define NSTAGE 3
#define GEMM_DSMEM (NSTAGE * STAGE_BYTES + 128)

extern __shared__ char dynsm[];

template<int AF32>
__global__ __launch_bounds__(256, 2) void mma_gemm_t(
    const half_t* __restrict__ A, Ptr5 ainp,
    const half_t* __restrict__ B,
    long bseg_stride, int nseg, Ptr5 pb,
    half_t* __restrict__ Ch,
    const float* __restrict__ a_s, const float* __restrict__ a_d,
    float* __restrict__ pas8, float* __restrict__ pad8,
    int M, int N, int K)
{
    char* smp = (char*)(((uintptr_t)dynsm + 127) & ~(uintptr_t)127);
    const uint32_t sb = smem_u32(smp);

    const int tid = threadIdx.x, wid = tid >> 5, lane = tid & 31;
    const int bx = blockIdx.x, by = blockIdx.y;
    const int m0 = (wid & 3) * 32, n0 = (wid >> 2) * 64;

    int seg = 0;
    if (nseg > 1) { seg = (by * 128) >> 13; if (seg > 4) seg = 4; }
    const half_t* Bs = B + (size_t)seg * bseg_stride;

    __shared__ float sbias[128], sas[128], sad[128];
    __shared__ float sredS[8][32], sredD[8][32];
    if (tid < 128) {
        sbias[tid] = pb.p[0] ? pb.p[seg][bx * 128 + tid] : 0.f;
        if (a_s) { sas[tid] = a_s[bx * 128 + tid]; sad[tid] = a_d[bx * 128 + tid]; }
    }

    const int r_ = tid >> 2, q_ = tid & 3;
    const uint32_t so0 = sw_off(r_, q_), so1 = sw_off(r_ + 64, q_);
    const size_t rs = (size_t)64 * K;

    const half_t* gA = nullptr;
    const float* gA32 = nullptr;
    if (AF32) {
        int segstart = (seg < 4) ? seg * 8192 : 32768;
        gA32 = ainp.p[seg] + (size_t)(by * 128 + r_ - segstart) * K + q_ * 8;
    } else {
        gA = A + (size_t)(by * 128 + r_) * K + q_ * 8;
    }
    const half_t* gB = Bs + (size_t)(bx * 128 + r_) * K + q_ * 8;

    const int nch = K / 64;

    auto load_chunk_B = [&](int ck) {
        const uint32_t st = sb + (ck % NSTAGE) * STAGE_BYTES;
        const int kb = ck * 64;
        if (!AF32) {
            cpa16(st + so0,        gA + kb);
            cpa16(st + so1,        gA + rs + kb);
            cpa16(st + 8192 + so0, gA + kb + 32);
            cpa16(st + 8192 + so1, gA + rs + kb + 32);
        }
        cpa16(st + 16384 + so0, gB + kb);
        cpa16(st + 16384 + so1, gB + rs + kb);
        cpa16(st + 24576 + so0, gB + kb + 32);
        cpa16(st + 24576 + so1, gB + rs + kb + 32);
        CP_COMMIT();
    };

    float4 ar[2][2][2];   // AF32: [row 0/1][sub 0/1][float4 lo/hi]
    auto ldg_A32 = [&](int ck) {
        const int kb = ck * 64;
#pragma unroll
        for (int s = 0; s < 2; s++) {
            ar[0][s][0] = *(const float4*)(gA32 + kb + s * 32);
            ar[0][s][1] = *(const float4*)(gA32 + kb + s * 32 + 4);
            ar[1][s][0] = *(const float4*)(gA32 + rs + kb + s * 32);
            ar[1][s][1] = *(const float4*)(gA32 + rs + kb + s * 32 + 4);
        }
    };

    float acc[2][8][4];
#pragma unroll
    for (int mt = 0; mt < 2; mt++)
#pragma unroll
        for (int nt = 0; nt < 8; nt++)
#pragma unroll
            for (int k = 0; k < 4; k++) acc[mt][nt][k] = 0.f;

    load_chunk_B(0);
    if (nch > 1) load_chunk_B(1);
    if (AF32) ldg_A32(0);

    const int tile = lane >> 3, rit = lane & 7;

    for (int c = 0; c < nch; c++) {
        if (AF32) {
            char* stg = smp + (c % NSTAGE) * STAGE_BYTES;
            *(uint4*)(stg + so0)        = pack8h(ar[0][0][0], ar[0][0][1]);
            *(uint4*)(stg + so1)        = pack8h(ar[1][0][0], ar[1][0][1]);
            *(uint4*)(stg + 8192 + so0) = pack8h(ar[0][1][0], ar[0][1][1]);
            *(uint4*)(stg + 8192 + so1) = pack8h(ar[1][1][0], ar[1][1][1]);
        }
        const int rem = nch - 1 - c;
        if (rem >= 1) asm volatile("cp.async.wait_group 1;" ::: "memory");
        else          asm volatile("cp.async.wait_group 0;" ::: "memory");
        __syncthreads();
        if (c + 2 < nch) load_chunk_B(c + 2);
        if (AF32 && c + 1 < nch) ldg_A32(c + 1);

        const uint32_t sbase = sb + (c % NSTAGE) * STAGE_BYTES;
#pragma unroll
        for (int ks = 0; ks < 4; ks++) {
            const uint32_t asub = sbase + (ks >> 1) * 8192;
            const uint32_t bsub = sbase + 16384 + (ks >> 1) * 8192;
            const int kk = ks & 1;
            uint32_t af[2][4];
#pragma unroll
            for (int mt = 0; mt < 2; mt++) {
                int row = m0 + mt * 16 + (tile & 1) * 8 + rit;
                ldsm_x4(af[mt], asub + sw_off(row, kk * 2 + (tile >> 1)));
            }
#pragma unroll
            for (int p = 0; p < 4; p++) {
                int row = n0 + p * 16 + (tile >> 1) * 8 + rit;
                uint32_t bh[4];
                ldsm_x4(bh, bsub + sw_off(row, kk * 2 + (tile & 1)));
#pragma unroll
                for (int mt = 0; mt < 2; mt++) {
                    mma_f16(acc[mt][p * 2 + 0], af[mt], bh[0], bh[1]);
                    mma_f16(acc[mt][p * 2 + 1], af[mt], bh[2], bh[3]);
                }
            }
        }
        if (AF32) __syncthreads();
    }

    // epilogue: bias + fp16 store
#pragma unroll
    for (int mt = 0; mt < 2; mt++) {
        const int r = by * 128 + m0 + mt * 16 + (lane >> 2);
#pragma unroll
        for (int nt = 0; nt < 8; nt++) {
            const int cl = n0 + nt * 8 + (lane & 3) * 2;
            const int cg = bx * 128 + cl;
            float v0 = acc[mt][nt][0] + sbias[cl];
            float v1 = acc[mt][nt][1] + sbias[cl + 1];
            float v2 = acc[mt][nt][2] + sbias[cl];
            float v3 = acc[mt][nt][3] + sbias[cl + 1];
            *(__half2*)(Ch + (size_t)r * N + cg) = __floats2half2_rn(v0, v1);
            *(__half2*)(Ch + (size_t)(r + 8) * N + cg) = __floats2half2_rn(v2, v3);
        }
    }

    if (a_s) {
        float sp[2][2] = {{0.f, 0.f}, {0.f, 0.f}};
        float dp[2][2] = {{0.f, 0.f}, {0.f, 0.f}};
#pragma unroll
        for (int mt = 0; mt < 2; mt++)
#pragma unroll
            for (int nt = 0; nt < 8; nt++) {
                const int cl = n0 + nt * 8 + (lane & 3) * 2;
                sp[mt][0] += acc[mt][nt][0] * sas[cl] + acc[mt][nt][1] * sas[cl + 1];
                dp[mt][0] += acc[mt][nt][0] * sad[cl] + acc[mt][nt][1] * sad[cl + 1];
                sp[mt][1] += acc[mt][nt][2] * sas[cl] + acc[mt][nt][3] * sas[cl + 1];
                dp[mt][1] += acc[mt][nt][2] * sad[cl] + acc[mt][nt][3] * sad[cl + 1];
            }
#pragma unroll
        for (int mt = 0; mt < 2; mt++)
#pragma unroll
            for (int h8 = 0; h8 < 2; h8++) {
                float s = sp[mt][h8], d = dp[mt][h8];
                s += __shfl_xor_sync(0xffffffffu, s, 1);
                s += __shfl_xor_sync(0xffffffffu, s, 2);
                d += __shfl_xor_sync(0xffffffffu, d, 1);
                d += __shfl_xor_sync(0xffffffffu, d, 2);
                if ((lane & 3) == 0) {
                    int rw = mt * 16 + h8 * 8 + (lane >> 2);
                    sredS[wid][rw] = s;
                    sredD[wid][rw] = d;
                }
            }
        __syncthreads();
        if (wid < 4) {
            float s = sredS[wid][lane] + sredS[wid + 4][lane];
            float d = sredD[wid][lane] + sredD[wid + 4][lane];
            int n = by * 128 + wid * 32 + lane;
            pas8[n * 8 + bx] = s;
            pad8[n * 8 + bx] = d;
        }
    }
}

// ---------------------------------------------------------------------------
// Alpha helpers
// ---------------------------------------------------------------------------
__device__ __forceinline__ float rd_as(const float* p8, int n, int hd) {
    return p8[n * 8 + 2 * hd] + p8[n * 8 + 2 * hd + 1];
}

// ---------------------------------------------------------------------------
// Strip aggregation (concat layers).
// grid = 4096 (region strips of 2 timesteps) + 8192 (audio even/odd pairs).
// ---------------------------------------------------------------------------
__global__ __launch_bounds__(256, 4) void agg_strip_kernel(
    const half_t* __restrict__ h, const float* __restrict__ pas8,
    const float* __restrict__ pad8, const float* __restrict__ bias,
    half_t* __restrict__ outA)
{
    const int bid = blockIdx.x, tid = threadIdx.x;
    if (bid < 4096) {
        const int bt0 = bid * 2;
        const int t0 = bt0 & 511;
        __shared__ float wc[2][4][4][4];
        __shared__ float wp[2][4][4];
        if (tid < 32) {
            int tt = tid >> 4, j = (tid >> 2) & 3, hd = tid & 3;
            int bt = bt0 + tt, t = t0 + tt;
            int n = j * 8192 + bt;
            float adv = rd_as(pad8, n, hd);
            float e[5]; int ei[3]; int cnt = 0;
            for (int i = 0; i < 4; i++)
                if (i != j) { e[cnt] = rd_as(pas8, i * 8192 + bt, hd) + adv; ei[cnt] = i; cnt++; }
            int prevIdx = -1;
            if (t > 0) { e[cnt] = rd_as(pas8, n - 1, hd) + adv; prevIdx = cnt; cnt++; }
            int selfIdx = cnt; e[cnt] = rd_as(pas8, n, hd) + adv; cnt++;
            float m = -1e30f;
            for (int k = 0; k < cnt; k++) { float v = e[k]; v = v >= 0.f ? v : 0.2f * v; e[k] = v; m = fmaxf(m, v); }
            float den = 0.f;
            for (int k = 0; k < cnt; k++) { e[k] = __expf(e[k] - m); den += e[k]; }
            float inv = 1.f / (den + 1e-16f);
            float w4[4] = {0.f, 0.f, 0.f, 0.f};
            for (int k = 0; k < 3; k++) w4[ei[k]] = e[k] * inv;
            w4[j] = e[selfIdx] * inv;
            for (int i = 0; i < 4; i++) wc[tt][j][hd][i] = w4[i];
            wp[tt][j][hd] = (prevIdx >= 0) ? e[prevIdx] * inv : 0.f;
        }
        __syncthreads();
        const int c4 = tid * 4;
        const int hd = c4 >> 8;
        float4 bb = *(const float4*)&bias[c4];
        float4 prv[4];
        if (t0 > 0) {
#pragma unroll
            for (int i = 0; i < 4; i++)
                prv[i] = ld_h4(h + (size_t)(i * 8192 + bt0 - 1) * 1024 + c4);
        } else {
#pragma unroll
            for (int i = 0; i < 4; i++) prv[i] = make_float4(0.f, 0.f, 0.f, 0.f);
        }
#pragma unroll
        for (int tt = 0; tt < 2; tt++) {
            const int bt = bt0 + tt;
            float4 cur[4];
#pragma unroll
            for (int i = 0; i < 4; i++)
                cur[i] = ld_h4(h + (size_t)(i * 8192 + bt) * 1024 + c4);
#pragma unroll
            for (int j = 0; j < 4; j++) {
                float w0 = wc[tt][j][hd][0], w1 = wc[tt][j][hd][1];
                float w2 = wc[tt][j][hd][2], w3 = wc[tt][j][hd][3], wpp = wp[tt][j][hd];
                float4 o;
                o.x = w0 * cur[0].x + w1 * cur[1].x + w2 * cur[2].x + w3 * cur[3].x + wpp * prv[j].x + bb.x;
                o.y = w0 * cur[0].y + w1 * cur[1].y + w2 * cur[2].y + w3 * cur[3].y + wpp * prv[j].y + bb.y;
                o.z = w0 * cur[0].z + w1 * cur[1].z + w2 * cur[2].z + w3 * cur[3].z + wpp * prv[j].z + bb.z;
                o.w = w0 * cur[0].w + w1 * cur[1].w + w2 * cur[2].w + w3 * cur[3].w + wpp * prv[j].w + bb.w;
                st_h4(outA, (size_t)(j * 8192 + bt) * 1024 + c4, o);
            }
#pragma unroll
            for (int i = 0; i < 4; i++) prv[i] = cur[i];
        }
    } else {
        const int ap = bid - 4096;
        const int b = ap >> 9, tp = ap & 511;
        const int n0 = 32768 + b * 1024 + 2 * tp;
        const int bt = b * 512 + tp;
        __shared__ float al[4][3];
        if (tid < 4) {
            int hd = tid;
            int srcs[3] = { 8192 + bt, 16384 + bt, n0 };
            float adv = rd_as(pad8, n0, hd);
            float e[3], m = -1e30f;
            for (int k = 0; k < 3; k++) {
                float v = rd_as(pas8, srcs[k], hd) + adv;
                v = v >= 0.f ? v : 0.2f * v;
                e[k] = v; m = fmaxf(m, v);
            }
            float den = 0.f;
            for (int k = 0; k < 3; k++) { e[k] = __expf(e[k] - m); den += e[k]; }
            float inv = 1.f / (den + 1e-16f);
            for (int k = 0; k < 3; k++) al[hd][k] = e[k] * inv;
        }
        __syncthreads();
        const int c4 = tid * 4;
        const int hd = c4 >> 8;
        float4 bb = *(const float4*)&bias[c4];
        float4 vL = ld_h4(h + (size_t)(8192 + bt) * 1024 + c4);
        float4 vR = ld_h4(h + (size_t)(16384 + bt) * 1024 + c4);
        float4 vS = ld_h4(h + (size_t)n0 * 1024 + c4);
        float w0 = al[hd][0], w1 = al[hd][1], w2 = al[hd][2];
        float4 o;
        o.x = w0 * vL.x + w1 * vR.x + w2 * vS.x + bb.x;
        o.y = w0 * vL.y + w1 * vR.y + w2 * vS.y + bb.y;
        o.z = w0 * vL.z + w1 * vR.z + w2 * vS.z + bb.z;
        o.w = w0 * vL.w + w1 * vR.w + w2 * vS.w + bb.w;
        st_h4(outA, (size_t)n0 * 1024 + c4, o);
        float4 vO = ld_h4(h + (size_t)(n0 + 1) * 1024 + c4);
        float4 o2 = make_float4(vO.x + bb.x, vO.y + bb.y, vO.z + bb.z, vO.w + bb.w);
        st_h4(outA, (size_t)(n0 + 1) * 1024 + c4, o2);
    }
}

// ---------------------------------------------------------------------------
// Fused: head-mean aggregation (layer 2) + LayerNorm + per-batch mean partial.
// ---------------------------------------------------------------------------
__device__ __forceinline__ void ln_atomic_row(
    float o, int tid, int warp, int lane, float (*red)[8],
    const float* ln_g, const float* ln_b, float* part, int b_out)
{
    float s = o, q = o * o;
#pragma unroll
    for (int off = 16; off; off >>= 1) {
        s += __shfl_xor_sync(0xffffffffu, s, off);
        q += __shfl_xor_sync(0xffffffffu, q, off);
    }
    if (lane == 0) { red[0][warp] = s; red[1][warp] = q; }
    __syncthreads();
    float ts = 0.f, tq = 0.f;
#pragma unroll
    for (int w = 0; w < 8; w++) { ts += red[0][w]; tq += red[1][w]; }
    float mu = ts * (1.f / 256.f);
    float var = tq * (1.f / 256.f) - mu * mu;
    float rstd = rsqrtf(var + 1e-5f);
    float v = (o - mu) * rstd * ln_g[tid] + ln_b[tid];
    atomicAdd(&part[b_out * 256 + tid], v);
    __syncthreads();
}

__global__ __launch_bounds__(256, 4) void agg_mean_ln_kernel(
    const half_t* __restrict__ h, const float* __restrict__ pas8,
    const float* __restrict__ pad8, const float* __restrict__ bias,
    const float* __restrict__ ln_g, const float* __restrict__ ln_b,
    float* __restrict__ part)
{
    const int bid = blockIdx.x, tid = threadIdx.x;
    const int warp = tid >> 5, lane = tid & 31;
    __shared__ float red[2][8];
    if (bid < 8192) {
        const int bt = bid, t = bt & 511;
        __shared__ float wcur[4][4][4];
        __shared__ float wprev[4][4];
        if (tid < 16) {
            int j = tid >> 2, hd = tid & 3;
            int n = j * 8192 + bt;
            float adv = rd_as(pad8, n, hd);
            float e[5]; int ei[3]; int cnt = 0;
            for (int i = 0; i < 4; i++)
                if (i != j) { e[cnt] = rd_as(pas8, i * 8192 + bt, hd) + adv; ei[cnt] = i; cnt++; }
            int prevIdx = -1;
            if (t > 0) { e[cnt] = rd_as(pas8, n - 1, hd) + adv; prevIdx = cnt; cnt++; }
            int selfIdx = cnt; e[cnt] = rd_as(pas8, n, hd) + adv; cnt++;
            float m = -1e30f;
            for (int k = 0; k < cnt; k++) { float v = e[k]; v = v >= 0.f ? v : 0.2f * v; e[k] = v; m = fmaxf(m, v); }
            float den = 0.f;
            for (int k = 0; k < cnt; k++) { e[k] = __expf(e[k] - m); den += e[k]; }
            float inv = 1.f / (den + 1e-16f);
            float wcv[4] = {0.f, 0.f, 0.f, 0.f};
            for (int k = 0; k < 3; k++) wcv[ei[k]] = e[k] * inv;
            wcv[j] = e[selfIdx] * inv;
            for (int i = 0; i < 4; i++) wcur[j][hd][i] = wcv[i];
            wprev[j][hd] = (prevIdx >= 0) ? e[prevIdx] * inv : 0.f;
        }
        __syncthreads();
        __shared__ float sm[4][4][256];
        const int hd = tid >> 6, cb = (tid & 63) * 4;
        float4 cur[4], prv[4];
#pragma unroll
        for (int i = 0; i < 4; i++)
            cur[i] = ld_h4(h + (size_t)(i * 8192 + bt) * 1024 + hd * 256 + cb);
        if (t > 0) {
#pragma unroll
            for (int i = 0; i < 4; i++)
                prv[i] = ld_h4(h + (size_t)(i * 8192 + bt - 1) * 1024 + hd * 256 + cb);
        } else {
#pragma unroll
            for (int i = 0; i < 4; i++) prv[i] = make_float4(0.f, 0.f, 0.f, 0.f);
        }
#pragma unroll
        for (int j = 0; j < 4; j++) {
            float w0 = wcur[j][hd][0], w1 = wcur[j][hd][1];
            float w2 = wcur[j][hd][2], w3 = wcur[j][hd][3], wpp = wprev[j][hd];
            float4 o;
            o.x = w0 * cur[0].x + w1 * cur[1].x + w2 * cur[2].x + w3 * cur[3].x + wpp * prv[j].x;
            o.y = w0 * cur[0].y + w1 * cur[1].y + w2 * cur[2].y + w3 * cur[3].y + wpp * prv[j].y;
            o.z = w0 * cur[0].z + w1 * cur[1].z + w2 * cur[2].z + w3 * cur[3].z + wpp * prv[j].z;
            o.w = w0 * cur[0].w + w1 * cur[1].w + w2 * cur[2].w + w3 * cur[3].w + wpp * prv[j].w;
            *(float4*)&sm[hd][j][cb] = o;
        }
        __syncthreads();
#pragma unroll
        for (int j = 0; j < 4; j++) {
            float o = (sm[0][j][tid] + sm[1][j][tid] + sm[2][j][tid] + sm[3][j][tid]) * 0.25f
                    + bias[tid];
            int n = j * 8192 + bt;
            ln_atomic_row(o, tid, warp, lane, red, ln_g, ln_b, part, n / 3072);
        }
    } else {
        const int ap = bid - 8192;
        const int b = ap >> 9, tp = ap & 511;
        const int n0 = 32768 + b * 1024 + 2 * tp;
        const int bt = b * 512 + tp;
        __shared__ float al[4][3];
        if (tid < 4) {
            int hd = tid;
            int srcs[3] = { 8192 + bt, 16384 + bt, n0 };
            float adv = rd_as(pad8, n0, hd);
            float e[3], m = -1e30f;
            for (int k = 0; k < 3; k++) {
                float v = rd_as(pas8, srcs[k], hd) + adv;
                v = v >= 0.f ? v : 0.2f * v;
                e[k] = v; m = fmaxf(m, v);
            }
            float den = 0.f;
            for (int k = 0; k < 3; k++) { e[k] = __expf(e[k] - m); den += e[k]; }
            float inv = 1.f / (den + 1e-16f);
            for (int k = 0; k < 3; k++) al[hd][k] = e[k] * inv;
        }
        __syncthreads();
        __shared__ float sm2[2][4][256];
        const int hd = tid >> 6, cb = (tid & 63) * 4;
        {
            float4 vL = ld_h4(h + (size_t)(8192 + bt) * 1024 + hd * 256 + cb);
            float4 vR = ld_h4(h + (size_t)(16384 + bt) * 1024 + hd * 256 + cb);
            float4 vS = ld_h4(h + (size_t)n0 * 1024 + hd * 256 + cb);
            float w0 = al[hd][0], w1 = al[hd][1], w2 = al[hd][2];
            float4 o;
            o.x = w0 * vL.x + w1 * vR.x + w2 * vS.x;
            o.y = w0 * vL.y + w1 * vR.y + w2 * vS.y;
            o.z = w0 * vL.z + w1 * vR.z + w2 * vS.z;
            o.w = w0 * vL.w + w1 * vR.w + w2 * vS.w;
            *(float4*)&sm2[0][hd][cb] = o;
        }
        {
            float4 vO = ld_h4(h + (size_t)(n0 + 1) * 1024 + hd * 256 + cb);
            *(float4*)&sm2[1][hd][cb] = vO;
        }
        __syncthreads();
#pragma unroll
        for (int e = 0; e < 2; e++) {
            float o = (sm2[e][0][tid] + sm2[e][1][tid] + sm2[e][2][tid] + sm2[e][3][tid]) * 0.25f
                    + bias[tid];
            int n = n0 + e;
            ln_atomic_row(o, tid, warp, lane, red, ln_g, ln_b, part, n / 3072);
        }
    }
}

__global__ void reduce_out_kernel(const float* __restrict__ part, float* __restrict__ out)
{
    int b = blockIdx.x, c = threadIdx.x;
    out[b * 256 + c] = part[b * 256 + c] * (1.f / 3072.f);
}

// ---------------------------------------------------------------------------
// Launch
// ---------------------------------------------------------------------------
extern "C" void kernel_launch(void* const* d_in, const int* in_sizes, int n_in,
                              void* d_out, int out_size)
{
    Ptr5 inp = {{ (const float*)d_in[0], (const float*)d_in[1], (const float*)d_in[2],
                  (const float*)d_in[3], (const float*)d_in[4] }};
    Ptr5 wP  = {{ (const float*)d_in[5], (const float*)d_in[7], (const float*)d_in[9],
                  (const float*)d_in[11], (const float*)d_in[13] }};
    Ptr5 projb = {{ (const float*)d_in[6], (const float*)d_in[8], (const float*)d_in[10],
                    (const float*)d_in[12], (const float*)d_in[14] }};
    Ptr5 nob = {{ nullptr, nullptr, nullptr, nullptr, nullptr }};
    const float* W0 = (const float*)d_in[15];
    const float* as0 = (const float*)d_in[16];
    const float* ad0 = (const float*)d_in[17];
    const float* bias0 = (const float*)d_in[18];
    const float* W1 = (const float*)d_in[19];
    const float* as1 = (const float*)d_in[20];
    const float* ad1 = (const float*)d_in[21];
    const float* bias1 = (const float*)d_in[22];
    const float* W2 = (const float*)d_in[23];
    const float* as2 = (const float*)d_in[24];
    const float* ad2 = (const float*)d_in[25];
    const float* bias2 = (const float*)d_in[26];
    const float* ln_g = (const float*)d_in[27];
    const float* ln_b = (const float*)d_in[28];
    float* out = (float*)d_out;

    float *pas8, *pad8, *part;
    half_t *hh, *a0, *a1, *wh;
    cudaGetSymbolAddress((void**)&hh, g_hh);
    cudaGetSymbolAddress((void**)&pas8, g_pas8);
    cudaGetSymbolAddress((void**)&pad8, g_pad8);
    cudaGetSymbolAddress((void**)&part, g_part);
    cudaGetSymbolAddress((void**)&a0, g_a0);
    cudaGetSymbolAddress((void**)&a1, g_a1);
    cudaGetSymbolAddress((void**)&wh, g_wh);

    cudaFuncSetAttribute(mma_gemm_t<0>, cudaFuncAttributeMaxDynamicSharedMemorySize, GEMM_DSMEM);
    cudaFuncSetAttribute(mma_gemm_t<1>, cudaFuncAttributeMaxDynamicSharedMemorySize, GEMM_DSMEM);

    const size_t OFF_PROJ = 0;
    const size_t OFF_W0 = 5 * 131072;
    const size_t OFF_W1 = OFF_W0 + 262144;
    const size_t OFF_W2 = OFF_W1 + 1048576;

    // launch 0: weight prep + part zeroing
    prep_w_kernel<<<2945, 256>>>(wP, W0, W1, W2, wh, part);

    // launch 1: projections (fp32 A fused convert, batched 5 segments) -> a1
    mma_gemm_t<1><<<dim3(2, 384), 256, GEMM_DSMEM>>>(
        nullptr, inp, wh + OFF_PROJ, 131072, 5, projb,
        a1, nullptr, nullptr, nullptr, nullptr,
        NNODES, 256, 512);

    // launch 2: GAT layer 0 GEMM (K=256)
    mma_gemm_t<0><<<dim3(8, 384), 256, GEMM_DSMEM>>>(
        a1, nob, wh + OFF_W0, 0, 1, nob,
        hh, as0, ad0, pas8, pad8,
        NNODES, 1024, 256);
    // launch 3: aggregate 0
    agg_strip_kernel<<<12288, 256>>>(hh, pas8, pad8, bias0, a0);

    // launch 4: GAT layer 1 GEMM (K=1024)
    mma_gemm_t<0><<<dim3(8, 384), 256, GEMM_DSMEM>>>(
        a0, nob, wh + OFF_W1, 0, 1, nob,
        hh, as1, ad1, pas8, pad8,
        NNODES, 1024, 1024);
    // launch 5: aggregate 1
    agg_strip_kernel<<<12288, 256>>>(hh, pas8, pad8, bias1, a1);

    // launch 6: GAT layer 2 GEMM (K=1024)
    mma_gemm_t<0><<<dim3(8, 384), 256, GEMM_DSMEM>>>(
        a1, nob, wh + OFF_W2, 0, 1, nob,
        hh, as2, ad2, pas8, pad8,
        NNODES, 1024, 1024);
    // launch 7: fused head-mean aggregate + LayerNorm + batch-mean partials
    agg_mean_ln_kernel<<<16384, 256>>>(hh, pas8, pad8, bias2, ln_g, ln_b, part);

    // launch 8: final scale
    reduce_out_kernel<<<16, 256>>>(part, out);
}

// round 15
// speedup vs baseline: 1.4204x; 1.4204x over previous
#include <cuda_runtime.h>
#include <cuda_fp16.h>
#include <math.h>
#include <cstdint>

// ---------------------------------------------------------------------------
// Constants: B=16, T=512, TA=1024, NREG=4, D=512, HID=256, HEADS=4
// Region nodes: n = region*8192 + b*512 + t ; audio nodes: n = 32768 + b*1024 + ta
// ---------------------------------------------------------------------------
#define NNODES 49152

typedef __half half_t;

// Scratch (device globals)
__device__ half_t g_hh[(size_t)NNODES * 1024];    // GEMM output (fp16)
__device__ half_t g_a0[(size_t)NNODES * 1024];    // activations (ping)
__device__ half_t g_a1[(size_t)NNODES * 1024];    // activations (pong)
__device__ half_t g_wh[3014656];                  // weights fp16
__device__ float  g_pas8[NNODES * 8];
__device__ float  g_pad8[NNODES * 8];
__device__ float  g_part[16 * 256];               // per-batch accumulators

struct Ptr5 { const float* p[5]; };

// ---------------------------------------------------------------------------
// helpers
// ---------------------------------------------------------------------------
__device__ __forceinline__ uint32_t smem_u32(const void* p) {
    uint32_t a;
    asm("{ .reg .u64 t; cvta.to.shared.u64 t, %1; cvt.u32.u64 %0, t; }" : "=r"(a) : "l"(p));
    return a;
}
__device__ __forceinline__ uint32_t sw_off(int row, int c16) {
    int p = row >> 1;
    int c = ((row & 1) * 4 + c16) ^ (p & 7);
    return (uint32_t)(p * 128 + (c << 4));
}
__device__ __forceinline__ void ldsm_x4(uint32_t r[4], uint32_t addr) {
    asm volatile("ldmatrix.sync.aligned.m8n8.x4.shared.b16 {%0,%1,%2,%3}, [%4];"
                 : "=r"(r[0]), "=r"(r[1]), "=r"(r[2]), "=r"(r[3]) : "r"(addr));
}
__device__ __forceinline__ void mma_f16(float d[4], const uint32_t a[4],
                                        uint32_t b0, uint32_t b1) {
    asm volatile(
        "mma.sync.aligned.m16n8k16.row.col.f32.f16.f16.f32 "
        "{%0,%1,%2,%3}, {%4,%5,%6,%7}, {%8,%9}, {%0,%1,%2,%3};"
        : "+f"(d[0]), "+f"(d[1]), "+f"(d[2]), "+f"(d[3])
        : "r"(a[0]), "r"(a[1]), "r"(a[2]), "r"(a[3]), "r"(b0), "r"(b1));
}
__device__ __forceinline__ void cpa16(uint32_t sm, const void* g) {
    asm volatile("cp.async.cg.shared.global [%0], [%1], 16;" :: "r"(sm), "l"(g));
}
#define CP_COMMIT() asm volatile("cp.async.commit_group;" ::: "memory")

__device__ __forceinline__ float4 ld_h4(const half_t* p) {
    uint2 u = *(const uint2*)p;
    __half2 a = *reinterpret_cast<__half2*>(&u.x);
    __half2 b = *reinterpret_cast<__half2*>(&u.y);
    float2 fa = __half22float2(a), fb = __half22float2(b);
    return make_float4(fa.x, fa.y, fb.x, fb.y);
}
__device__ __forceinline__ void st_h4(half_t* P, size_t idx, float4 o) {
    __half2 h0 = __floats2half2_rn(o.x, o.y), h1 = __floats2half2_rn(o.z, o.w);
    uint2 u;
    u.x = *reinterpret_cast<uint32_t*>(&h0);
    u.y = *reinterpret_cast<uint32_t*>(&h1);
    *(uint2*)(P + idx) = u;
}
__device__ __forceinline__ uint4 pack8h(float4 a, float4 b) {
    __half2 h0 = __floats2half2_rn(a.x, a.y), h1 = __floats2half2_rn(a.z, a.w);
    __half2 h2 = __floats2half2_rn(b.x, b.y), h3 = __floats2half2_rn(b.z, b.w);
    uint4 u;
    u.x = *reinterpret_cast<uint32_t*>(&h0);
    u.y = *reinterpret_cast<uint32_t*>(&h1);
    u.z = *reinterpret_cast<uint32_t*>(&h2);
    u.w = *reinterpret_cast<uint32_t*>(&h3);
    return u;
}

// ---------------------------------------------------------------------------
// prep_w: weight transpose->fp16 (2944 blocks) + part zeroing (block 2944)
// ---------------------------------------------------------------------------
__device__ void tsp_block_h(const float* __restrict__ in, half_t* __restrict__ oh,
                            int R, int C, int gx, int gy, float (*tile)[33])
{
    int tx = threadIdx.x & 31, ty = threadIdx.x >> 5;
    int c0 = gx * 32, r0 = gy * 32;
    for (int i = ty; i < 32; i += 8)
        tile[i][tx] = in[(size_t)(r0 + i) * C + c0 + tx];
    __syncthreads();
    for (int i = ty; i < 32; i += 8)
        oh[(size_t)(c0 + i) * R + r0 + tx] = __float2half_rn(tile[tx][i]);
}

__global__ __launch_bounds__(256) void prep_w_kernel(
    Ptr5 wP, const float* __restrict__ W0, const float* __restrict__ W1,
    const float* __restrict__ W2, half_t* __restrict__ wh, float* __restrict__ part)
{
    __shared__ float tile[32][33];
    const size_t OFF_W0 = 5 * 131072;
    const size_t OFF_W1 = OFF_W0 + 262144;
    const size_t OFF_W2 = OFF_W1 + 1048576;
    int bid = blockIdx.x;
    if (bid == 2944) {
        for (int i = threadIdx.x; i < 16 * 256; i += 256) part[i] = 0.f;
        return;
    }
    if (bid < 640) {
        int i = bid >> 7, rem = bid & 127;
        tsp_block_h(wP.p[i], wh + (size_t)i * 131072, 512, 256, rem & 7, rem >> 3, tile);
    } else if (bid < 896) {
        int rem = bid - 640;
        tsp_block_h(W0, wh + OFF_W0, 256, 1024, rem & 31, rem >> 5, tile);
    } else if (bid < 1920) {
        int rem = bid - 896;
        tsp_block_h(W1, wh + OFF_W1, 1024, 1024, rem & 31, rem >> 5, tile);
    } else {
        int rem = bid - 1920;
        tsp_block_h(W2, wh + OFF_W2, 1024, 1024, rem & 31, rem >> 5, tile);
    }
}

// ---------------------------------------------------------------------------
// fp16 GEMM (round-10/12 proven config): C = A @ B^T (+bias), fp32 accumulate.
// CTA 128x128, 8 warps (4m x 2n), warp 32x64, K-chunk 32, 6-stage cp.async,
// 2 CTAs/SM. AF32=1: A read fp32 (segmented inputs) + in-register convert.
// Fused alpha dots -> pas8/pad8.
// ---------------------------------------------------------------------------
#define STAGE_BYTES 16384
#define NSTAGE 6
#define GEMM_DSMEM (NSTAGE * STAGE_BYTES + 128)

extern __shared__ char dynsm[];

template<int AF32>
__global__ __launch_bounds__(256, 2) void mma_gemm_t(
    const half_t* __restrict__ A, Ptr5 ainp,
    const half_t* __restrict__ B,
    long bseg_stride, int nseg, Ptr5 pb,
    half_t* __restrict__ Ch,
    const float* __restrict__ a_s, const float* __restrict__ a_d,
    float* __restrict__ pas8, float* __restrict__ pad8,
    int M, int N, int K)
{
    char* smp = (char*)(((uintptr_t)dynsm + 127) & ~(uintptr_t)127);
    const uint32_t sb = smem_u32(smp);

    const int tid = threadIdx.x, wid = tid >> 5, lane = tid & 31;
    const int bx = blockIdx.x, by = blockIdx.y;
    const int m0 = (wid & 3) * 32, n0 = (wid >> 2) * 64;

    int seg = 0;
    if (nseg > 1) { seg = (by * 128) >> 13; if (seg > 4) seg = 4; }
    const half_t* Bs = B + (size_t)seg * bseg_stride;

    __shared__ float sbias[128], sas[128], sad[128];
    __shared__ float sredS[8][32], sredD[8][32];
    if (tid < 128) {
        sbias[tid] = pb.p[0] ? pb.p[seg][bx * 128 + tid] : 0.f;
        if (a_s) { sas[tid] = a_s[bx * 128 + tid]; sad[tid] = a_d[bx * 128 + tid]; }
    }

    const int r_ = tid >> 2, q_ = tid & 3;
    const uint32_t so0 = sw_off(r_, q_), so1 = sw_off(r_ + 64, q_);
    const size_t rs = (size_t)64 * K;

    const half_t* gA = nullptr;
    const float* gA32 = nullptr;
    if (AF32) {
        int segstart = (seg < 4) ? seg * 8192 : 32768;
        gA32 = ainp.p[seg] + (size_t)(by * 128 + r_ - segstart) * K + q_ * 8;
    } else {
        gA = A + (size_t)(by * 128 + r_) * K + q_ * 8;
    }
    const half_t* gB = Bs + (size_t)(bx * 128 + r_) * K + q_ * 8;

    const int nch = K / 32;

    auto load_chunk_B = [&](int ck) {
        const uint32_t st = sb + (ck % NSTAGE) * STAGE_BYTES;
        const int kb = ck * 32;
        if (!AF32) {
            cpa16(st + so0,        gA + kb);
            cpa16(st + so1,        gA + rs + kb);
        }
        cpa16(st + 8192 + so0, gB + kb);
        cpa16(st + 8192 + so1, gB + rs + kb);
        CP_COMMIT();
    };

    float4 ar[2][2];
    auto ldg_A32 = [&](int ck) {
        const int kb = ck * 32;
        ar[0][0] = *(const float4*)(gA32 + kb);
        ar[0][1] = *(const float4*)(gA32 + kb + 4);
        ar[1][0] = *(const float4*)(gA32 + rs + kb);
        ar[1][1] = *(const float4*)(gA32 + rs + kb + 4);
    };

    float acc[2][8][4];
#pragma unroll
    for (int mt = 0; mt < 2; mt++)
#pragma unroll
        for (int nt = 0; nt < 8; nt++)
#pragma unroll
            for (int k = 0; k < 4; k++) acc[mt][nt][k] = 0.f;

#pragma unroll
    for (int pc = 0; pc < 5; pc++)
        if (pc < nch) load_chunk_B(pc);
    if (AF32) ldg_A32(0);

    const int tile = lane >> 3, rit = lane & 7;

    for (int c = 0; c < nch; c++) {
        if (AF32) {
            char* stg = smp + (c % NSTAGE) * STAGE_BYTES;
            *(uint4*)(stg + so0) = pack8h(ar[0][0], ar[0][1]);
            *(uint4*)(stg + so1) = pack8h(ar[1][0], ar[1][1]);
        }
        const int rem = nch - 1 - c;
        if (rem >= 4)      asm volatile("cp.async.wait_group 4;" ::: "memory");
        else if (rem == 3) asm volatile("cp.async.wait_group 3;" ::: "memory");
        else if (rem == 2) asm volatile("cp.async.wait_group 2;" ::: "memory");
        else if (rem == 1) asm volatile("cp.async.wait_group 1;" ::: "memory");
        else               asm volatile("cp.async.wait_group 0;" ::: "memory");
        __syncthreads();
        if (c + 5 < nch) load_chunk_B(c + 5);
        if (AF32 && c + 1 < nch) ldg_A32(c + 1);

        const uint32_t sbase = sb + (c % NSTAGE) * STAGE_BYTES;
#pragma unroll
        for (int ks = 0; ks < 2; ks++) {
            uint32_t af[2][4];
#pragma unroll
            for (int mt = 0; mt < 2; mt++) {
                int row = m0 + mt * 16 + (tile & 1) * 8 + rit;
                ldsm_x4(af[mt], sbase + sw_off(row, ks * 2 + (tile >> 1)));
            }
#pragma unroll
            for (int p = 0; p < 4; p++) {
                int row = n0 + p * 16 + (tile >> 1) * 8 + rit;
                uint32_t bh[4];
                ldsm_x4(bh, sbase + 8192 + sw_off(row, ks * 2 + (tile & 1)));
#pragma unroll
                for (int mt = 0; mt < 2; mt++) {
                    mma_f16(acc[mt][p * 2 + 0], af[mt], bh[0], bh[1]);
                    mma_f16(acc[mt][p * 2 + 1], af[mt], bh[2], bh[3]);
                }
            }
        }
        if (AF32) __syncthreads();
    }

    // epilogue: bias + fp16 store
#pragma unroll
    for (int mt = 0; mt < 2; mt++) {
        const int r = by * 128 + m0 + mt * 16 + (lane >> 2);
#pragma unroll
        for (int nt = 0; nt < 8; nt++) {
            const int cl = n0 + nt * 8 + (lane & 3) * 2;
            const int cg = bx * 128 + cl;
            float v0 = acc[mt][nt][0] + sbias[cl];
            float v1 = acc[mt][nt][1] + sbias[cl + 1];
            float v2 = acc[mt][nt][2] + sbias[cl];
            float v3 = acc[mt][nt][3] + sbias[cl + 1];
            *(__half2*)(Ch + (size_t)r * N + cg) = __floats2half2_rn(v0, v1);
            *(__half2*)(Ch + (size_t)(r + 8) * N + cg) = __floats2half2_rn(v2, v3);
        }
    }

    if (a_s) {
        float sp[2][2] = {{0.f, 0.f}, {0.f, 0.f}};
        float dp[2][2] = {{0.f, 0.f}, {0.f, 0.f}};
#pragma unroll
        for (int mt = 0; mt < 2; mt++)
#pragma unroll
            for (int nt = 0; nt < 8; nt++) {
                const int cl = n0 + nt * 8 + (lane & 3) * 2;
                sp[mt][0] += acc[mt][nt][0] * sas[cl] + acc[mt][nt][1] * sas[cl + 1];
                dp[mt][0] += acc[mt][nt][0] * sad[cl] + acc[mt][nt][1] * sad[cl + 1];
                sp[mt][1] += acc[mt][nt][2] * sas[cl] + acc[mt][nt][3] * sas[cl + 1];
                dp[mt][1] += acc[mt][nt][2] * sad[cl] + acc[mt][nt][3] * sad[cl + 1];
            }
#pragma unroll
        for (int mt = 0; mt < 2; mt++)
#pragma unroll
            for (int h8 = 0; h8 < 2; h8++) {
                float s = sp[mt][h8], d = dp[mt][h8];
                s += __shfl_xor_sync(0xffffffffu, s, 1);
                s += __shfl_xor_sync(0xffffffffu, s, 2);
                d += __shfl_xor_sync(0xffffffffu, d, 1);
                d += __shfl_xor_sync(0xffffffffu, d, 2);
                if ((lane & 3) == 0) {
                    int rw = mt * 16 + h8 * 8 + (lane >> 2);
                    sredS[wid][rw] = s;
                    sredD[wid][rw] = d;
                }
            }
        __syncthreads();
        if (wid < 4) {
            float s = sredS[wid][lane] + sredS[wid + 4][lane];
            float d = sredD[wid][lane] + sredD[wid + 4][lane];
            int n = by * 128 + wid * 32 + lane;
            pas8[n * 8 + bx] = s;
            pad8[n * 8 + bx] = d;
        }
    }
}

// ---------------------------------------------------------------------------
// Alpha helpers
// ---------------------------------------------------------------------------
__device__ __forceinline__ float rd_as(const float* p8, int n, int hd) {
    return p8[n * 8 + 2 * hd] + p8[n * 8 + 2 * hd + 1];
}

// ---------------------------------------------------------------------------
// Strip aggregation (concat layers).
// grid = 4096 (region strips of 2 timesteps) + 8192 (audio even/odd pairs).
// ---------------------------------------------------------------------------
__global__ __launch_bounds__(256, 4) void agg_strip_kernel(
    const half_t* __restrict__ h, const float* __restrict__ pas8,
    const float* __restrict__ pad8, const float* __restrict__ bias,
    half_t* __restrict__ outA)
{
    const int bid = blockIdx.x, tid = threadIdx.x;
    if (bid < 4096) {
        const int bt0 = bid * 2;
        const int t0 = bt0 & 511;
        __shared__ float wc[2][4][4][4];
        __shared__ float wp[2][4][4];
        if (tid < 32) {
            int tt = tid >> 4, j = (tid >> 2) & 3, hd = tid & 3;
            int bt = bt0 + tt, t = t0 + tt;
            int n = j * 8192 + bt;
            float adv = rd_as(pad8, n, hd);
            float e[5]; int ei[3]; int cnt = 0;
            for (int i = 0; i < 4; i++)
                if (i != j) { e[cnt] = rd_as(pas8, i * 8192 + bt, hd) + adv; ei[cnt] = i; cnt++; }
            int prevIdx = -1;
            if (t > 0) { e[cnt] = rd_as(pas8, n - 1, hd) + adv; prevIdx = cnt; cnt++; }
            int selfIdx = cnt; e[cnt] = rd_as(pas8, n, hd) + adv; cnt++;
            float m = -1e30f;
            for (int k = 0; k < cnt; k++) { float v = e[k]; v = v >= 0.f ? v : 0.2f * v; e[k] = v; m = fmaxf(m, v); }
            float den = 0.f;
            for (int k = 0; k < cnt; k++) { e[k] = __expf(e[k] - m); den += e[k]; }
            float inv = 1.f / (den + 1e-16f);
            float w4[4] = {0.f, 0.f, 0.f, 0.f};
            for (int k = 0; k < 3; k++) w4[ei[k]] = e[k] * inv;
            w4[j] = e[selfIdx] * inv;
            for (int i = 0; i < 4; i++) wc[tt][j][hd][i] = w4[i];
            wp[tt][j][hd] = (prevIdx >= 0) ? e[prevIdx] * inv : 0.f;
        }
        __syncthreads();
        const int c4 = tid * 4;
        const int hd = c4 >> 8;
        float4 bb = *(const float4*)&bias[c4];
        float4 prv[4];
        if (t0 > 0) {
#pragma unroll
            for (int i = 0; i < 4; i++)
                prv[i] = ld_h4(h + (size_t)(i * 8192 + bt0 - 1) * 1024 + c4);
        } else {
#pragma unroll
            for (int i = 0; i < 4; i++) prv[i] = make_float4(0.f, 0.f, 0.f, 0.f);
        }
#pragma unroll
        for (int tt = 0; tt < 2; tt++) {
            const int bt = bt0 + tt;
            float4 cur[4];
#pragma unroll
            for (int i = 0; i < 4; i++)
                cur[i] = ld_h4(h + (size_t)(i * 8192 + bt) * 1024 + c4);
#pragma unroll
            for (int j = 0; j < 4; j++) {
                float w0 = wc[tt][j][hd][0], w1 = wc[tt][j][hd][1];
                float w2 = wc[tt][j][hd][2], w3 = wc[tt][j][hd][3], wpp = wp[tt][j][hd];
                float4 o;
                o.x = w0 * cur[0].x + w1 * cur[1].x + w2 * cur[2].x + w3 * cur[3].x + wpp * prv[j].x + bb.x;
                o.y = w0 * cur[0].y + w1 * cur[1].y + w2 * cur[2].y + w3 * cur[3].y + wpp * prv[j].y + bb.y;
                o.z = w0 * cur[0].z + w1 * cur[1].z + w2 * cur[2].z + w3 * cur[3].z + wpp * prv[j].z + bb.z;
                o.w = w0 * cur[0].w + w1 * cur[1].w + w2 * cur[2].w + w3 * cur[3].w + wpp * prv[j].w + bb.w;
                st_h4(outA, (size_t)(j * 8192 + bt) * 1024 + c4, o);
            }
#pragma unroll
            for (int i = 0; i < 4; i++) prv[i] = cur[i];
        }
    } else {
        const int ap = bid - 4096;
        const int b = ap >> 9, tp = ap & 511;
        const int n0 = 32768 + b * 1024 + 2 * tp;
        const int bt = b * 512 + tp;
        __shared__ float al[4][3];
        if (tid < 4) {
            int hd = tid;
            int srcs[3] = { 8192 + bt, 16384 + bt, n0 };
            float adv = rd_as(pad8, n0, hd);
            float e[3], m = -1e30f;
            for (int k = 0; k < 3; k++) {
                float v = rd_as(pas8, srcs[k], hd) + adv;
                v = v >= 0.f ? v : 0.2f * v;
                e[k] = v; m = fmaxf(m, v);
            }
            float den = 0.f;
            for (int k = 0; k < 3; k++) { e[k] = __expf(e[k] - m); den += e[k]; }
            float inv = 1.f / (den + 1e-16f);
            for (int k = 0; k < 3; k++) al[hd][k] = e[k] * inv;
        }
        __syncthreads();
        const int c4 = tid * 4;
        const int hd = c4 >> 8;
        float4 bb = *(const float4*)&bias[c4];
        float4 vL = ld_h4(h + (size_t)(8192 + bt) * 1024 + c4);
        float4 vR = ld_h4(h + (size_t)(16384 + bt) * 1024 + c4);
        float4 vS = ld_h4(h + (size_t)n0 * 1024 + c4);
        float w0 = al[hd][0], w1 = al[hd][1], w2 = al[hd][2];
        float4 o;
        o.x = w0 * vL.x + w1 * vR.x + w2 * vS.x + bb.x;
        o.y = w0 * vL.y + w1 * vR.y + w2 * vS.y + bb.y;
        o.z = w0 * vL.z + w1 * vR.z + w2 * vS.z + bb.z;
        o.w = w0 * vL.w + w1 * vR.w + w2 * vS.w + bb.w;
        st_h4(outA, (size_t)n0 * 1024 + c4, o);
        float4 vO = ld_h4(h + (size_t)(n0 + 1) * 1024 + c4);
        float4 o2 = make_float4(vO.x + bb.x, vO.y + bb.y, vO.z + bb.z, vO.w + bb.w);
        st_h4(outA, (size_t)(n0 + 1) * 1024 + c4, o2);
    }
}

// ---------------------------------------------------------------------------
// Fused: head-mean aggregation (layer 2) + LayerNorm + per-batch mean partial.
// ---------------------------------------------------------------------------
__device__ __forceinline__ void ln_atomic_row(
    float o, int tid, int warp, int lane, float (*red)[8],
    const float* ln_g, const float* ln_b, float* part, int b_out)
{
    float s = o, q = o * o;
#pragma unroll
    for (int off = 16; off; off >>= 1) {
        s += __shfl_xor_sync(0xffffffffu, s, off);
        q += __shfl_xor_sync(0xffffffffu, q, off);
    }
    if (lane == 0) { red[0][warp] = s; red[1][warp] = q; }
    __syncthreads();
    float ts = 0.f, tq = 0.f;
#pragma unroll
    for (int w = 0; w < 8; w++) { ts += red[0][w]; tq += red[1][w]; }
    float mu = ts * (1.f / 256.f);
    float var = tq * (1.f / 256.f) - mu * mu;
    float rstd = rsqrtf(var + 1e-5f);
    float v = (o - mu) * rstd * ln_g[tid] + ln_b[tid];
    atomicAdd(&part[b_out * 256 + tid], v);
    __syncthreads();
}

__global__ __launch_bounds__(256, 4) void agg_mean_ln_kernel(
    const half_t* __restrict__ h, const float* __restrict__ pas8,
    const float* __restrict__ pad8, const float* __restrict__ bias,
    const float* __restrict__ ln_g, const float* __restrict__ ln_b,
    float* __restrict__ part)
{
    const int bid = blockIdx.x, tid = threadIdx.x;
    const int warp = tid >> 5, lane = tid & 31;
    __shared__ float red[2][8];
    if (bid < 8192) {
        const int bt = bid, t = bt & 511;
        __shared__ float wcur[4][4][4];
        __shared__ float wprev[4][4];
        if (tid < 16) {
            int j = tid >> 2, hd = tid & 3;
            int n = j * 8192 + bt;
            float adv = rd_as(pad8, n, hd);
            float e[5]; int ei[3]; int cnt = 0;
            for (int i = 0; i < 4; i++)
                if (i != j) { e[cnt] = rd_as(pas8, i * 8192 + bt, hd) + adv; ei[cnt] = i; cnt++; }
            int prevIdx = -1;
            if (t > 0) { e[cnt] = rd_as(pas8, n - 1, hd) + adv; prevIdx = cnt; cnt++; }
            int selfIdx = cnt; e[cnt] = rd_as(pas8, n, hd) + adv; cnt++;
            float m = -1e30f;
            for (int k = 0; k < cnt; k++) { float v = e[k]; v = v >= 0.f ? v : 0.2f * v; e[k] = v; m = fmaxf(m, v); }
            float den = 0.f;
            for (int k = 0; k < cnt; k++) { e[k] = __expf(e[k] - m); den += e[k]; }
            float inv = 1.f / (den + 1e-16f);
            float wcv[4] = {0.f, 0.f, 0.f, 0.f};
            for (int k = 0; k < 3; k++) wcv[ei[k]] = e[k] * inv;
            wcv[j] = e[selfIdx] * inv;
            for (int i = 0; i < 4; i++) wcur[j][hd][i] = wcv[i];
            wprev[j][hd] = (prevIdx >= 0) ? e[prevIdx] * inv : 0.f;
        }
        __syncthreads();
        __shared__ float sm[4][4][256];
        const int hd = tid >> 6, cb = (tid & 63) * 4;
        float4 cur[4], prv[4];
#pragma unroll
        for (int i = 0; i < 4; i++)
            cur[i] = ld_h4(h + (size_t)(i * 8192 + bt) * 1024 + hd * 256 + cb);
        if (t > 0) {
#pragma unroll
            for (int i = 0; i < 4; i++)
                prv[i] = ld_h4(h + (size_t)(i * 8192 + bt - 1) * 1024 + hd * 256 + cb);
        } else {
#pragma unroll
            for (int i = 0; i < 4; i++) prv[i] = make_float4(0.f, 0.f, 0.f, 0.f);
        }
#pragma unroll
        for (int j = 0; j < 4; j++) {
            float w0 = wcur[j][hd][0], w1 = wcur[j][hd][1];
            float w2 = wcur[j][hd][2], w3 = wcur[j][hd][3], wpp = wprev[j][hd];
            float4 o;
            o.x = w0 * cur[0].x + w1 * cur[1].x + w2 * cur[2].x + w3 * cur[3].x + wpp * prv[j].x;
            o.y = w0 * cur[0].y + w1 * cur[1].y + w2 * cur[2].y + w3 * cur[3].y + wpp * prv[j].y;
            o.z = w0 * cur[0].z + w1 * cur[1].z + w2 * cur[2].z + w3 * cur[3].z + wpp * prv[j].z;
            o.w = w0 * cur[0].w + w1 * cur[1].w + w2 * cur[2].w + w3 * cur[3].w + wpp * prv[j].w;
            *(float4*)&sm[hd][j][cb] = o;
        }
        __syncthreads();
#pragma unroll
        for (int j = 0; j < 4; j++) {
            float o = (sm[0][j][tid] + sm[1][j][tid] + sm[2][j][tid] + sm[3][j][tid]) * 0.25f
                    + bias[tid];
            int n = j * 8192 + bt;
            ln_atomic_row(o, tid, warp, lane, red, ln_g, ln_b, part, n / 3072);
        }
    } else {
        const int ap = bid - 8192;
        const int b = ap >> 9, tp = ap & 511;
        const int n0 = 32768 + b * 1024 + 2 * tp;
        const int bt = b * 512 + tp;
        __shared__ float al[4][3];
        if (tid < 4) {
            int hd = tid;
            int srcs[3] = { 8192 + bt, 16384 + bt, n0 };
            float adv = rd_as(pad8, n0, hd);
            float e[3], m = -1e30f;
            for (int k = 0; k < 3; k++) {
                float v = rd_as(pas8, srcs[k], hd) + adv;
                v = v >= 0.f ? v : 0.2f * v;
                e[k] = v; m = fmaxf(m, v);
            }
            float den = 0.f;
            for (int k = 0; k < 3; k++) { e[k] = __expf(e[k] - m); den += e[k]; }
            float inv = 1.f / (den + 1e-16f);
            for (int k = 0; k < 3; k++) al[hd][k] = e[k] * inv;
        }
        __syncthreads();
        __shared__ float sm2[2][4][256];
        const int hd = tid >> 6, cb = (tid & 63) * 4;
        {
            float4 vL = ld_h4(h + (size_t)(8192 + bt) * 1024 + hd * 256 + cb);
            float4 vR = ld_h4(h + (size_t)(16384 + bt) * 1024 + hd * 256 + cb);
            float4 vS = ld_h4(h + (size_t)n0 * 1024 + hd * 256 + cb);
            float w0 = al[hd][0], w1 = al[hd][1], w2 = al[hd][2];
            float4 o;
            o.x = w0 * vL.x + w1 * vR.x + w2 * vS.x;
            o.y = w0 * vL.y + w1 * vR.y + w2 * vS.y;
            o.z = w0 * vL.z + w1 * vR.z + w2 * vS.z;
            o.w = w0 * vL.w + w1 * vR.w + w2 * vS.w;
            *(float4*)&sm2[0][hd][cb] = o;
        }
        {
            float4 vO = ld_h4(h + (size_t)(n0 + 1) * 1024 + hd * 256 + cb);
            *(float4*)&sm2[1][hd][cb] = vO;
        }
        __syncthreads();
#pragma unroll
        for (int e = 0; e < 2; e++) {
            float o = (sm2[e][0][tid] + sm2[e][1][tid] + sm2[e][2][tid] + sm2[e][3][tid]) * 0.25f
                    + bias[tid];
            int n = n0 + e;
            ln_atomic_row(o, tid, warp, lane, red, ln_g, ln_b, part, n / 3072);
        }
    }
}

__global__ void reduce_out_kernel(const float* __restrict__ part, float* __restrict__ out)
{
    int b = blockIdx.x, c = threadIdx.x;
    out[b * 256 + c] = part[b * 256 + c] * (1.f / 3072.f);
}

// ---------------------------------------------------------------------------
// Launch
// ---------------------------------------------------------------------------
extern "C" void kernel_launch(void* const* d_in, const int* in_sizes, int n_in,
                              void* d_out, int out_size)
{
    Ptr5 inp = {{ (const float*)d_in[0], (const float*)d_in[1], (const float*)d_in[2],
                  (const float*)d_in[3], (const float*)d_in[4] }};
    Ptr5 wP  = {{ (const float*)d_in[5], (const float*)d_in[7], (const float*)d_in[9],
                  (const float*)d_in[11], (const float*)d_in[13] }};
    Ptr5 projb = {{ (const float*)d_in[6], (const float*)d_in[8], (const float*)d_in[10],
                    (const float*)d_in[12], (const float*)d_in[14] }};
    Ptr5 nob = {{ nullptr, nullptr, nullptr, nullptr, nullptr }};
    const float* W0 = (const float*)d_in[15];
    const float* as0 = (const float*)d_in[16];
    const float* ad0 = (const float*)d_in[17];
    const float* bias0 = (const float*)d_in[18];
    const float* W1 = (const float*)d_in[19];
    const float* as1 = (const float*)d_in[20];
    const float* ad1 = (const float*)d_in[21];
    const float* bias1 = (const float*)d_in[22];
    const float* W2 = (const float*)d_in[23];
    const float* as2 = (const float*)d_in[24];
    const float* ad2 = (const float*)d_in[25];
    const float* bias2 = (const float*)d_in[26];
    const float* ln_g = (const float*)d_in[27];
    const float* ln_b = (const float*)d_in[28];
    float* out = (float*)d_out;

    float *pas8, *pad8, *part;
    half_t *hh, *a0, *a1, *wh;
    cudaGetSymbolAddress((void**)&hh, g_hh);
    cudaGetSymbolAddress((void**)&pas8, g_pas8);
    cudaGetSymbolAddress((void**)&pad8, g_pad8);
    cudaGetSymbolAddress((void**)&part, g_part);
    cudaGetSymbolAddress((void**)&a0, g_a0);
    cudaGetSymbolAddress((void**)&a1, g_a1);
    cudaGetSymbolAddress((void**)&wh, g_wh);

    cudaFuncSetAttribute(mma_gemm_t<0>, cudaFuncAttributeMaxDynamicSharedMemorySize, GEMM_DSMEM);
    cudaFuncSetAttribute(mma_gemm_t<1>, cudaFuncAttributeMaxDynamicSharedMemorySize, GEMM_DSMEM);

    const size_t OFF_PROJ = 0;
    const size_t OFF_W0 = 5 * 131072;
    const size_t OFF_W1 = OFF_W0 + 262144;
    const size_t OFF_W2 = OFF_W1 + 1048576;

    // launch 0: weight prep + part zeroing
    prep_w_kernel<<<2945, 256>>>(wP, W0, W1, W2, wh, part);

    // launch 1: projections (fp32 A fused convert, batched 5 segments) -> a1
    mma_gemm_t<1><<<dim3(2, 384), 256, GEMM_DSMEM>>>(
        nullptr, inp, wh + OFF_PROJ, 131072, 5, projb,
        a1, nullptr, nullptr, nullptr, nullptr,
        NNODES, 256, 512);

    // launch 2: GAT layer 0 GEMM (K=256)
    mma_gemm_t<0><<<dim3(8, 384), 256, GEMM_DSMEM>>>(
        a1, nob, wh + OFF_W0, 0, 1, nob,
        hh, as0, ad0, pas8, pad8,
        NNODES, 1024, 256);
    // launch 3: aggregate 0
    agg_strip_kernel<<<12288, 256>>>(hh, pas8, pad8, bias0, a0);

    // launch 4: GAT layer 1 GEMM (K=1024)
    mma_gemm_t<0><<<dim3(8, 384), 256, GEMM_DSMEM>>>(
        a0, nob, wh + OFF_W1, 0, 1, nob,
        hh, as1, ad1, pas8, pad8,
        NNODES, 1024, 1024);
    // launch 5: aggregate 1
    agg_strip_kernel<<<12288, 256>>>(hh, pas8, pad8, bias1, a1);

    // launch 6: GAT layer 2 GEMM (K=1024)
    mma_gemm_t<0><<<dim3(8, 384), 256, GEMM_DSMEM>>>(
        a1, nob, wh + OFF_W2, 0, 1, nob,
        hh, as2, ad2, pas8, pad8,
        NNODES, 1024, 1024);
    // launch 7: fused head-mean aggregate + LayerNorm + batch-mean partials
    agg_mean_ln_kernel<<<16384, 256>>>(hh, pas8, pad8, bias2, ln_g, ln_b, part);

    // launch 8: final scale
    reduce_out_kernel<<<16, 256>>>(part, out);
}

// round 16
// speedup vs baseline: 1.4386x; 1.0127x over previous
#include <cuda_runtime.h>
#include <cuda_fp16.h>
#include <math.h>
#include <cstdint>

// ---------------------------------------------------------------------------
// Constants: B=16, T=512, TA=1024, NREG=4, D=512, HID=256, HEADS=4
// Region nodes: n = region*8192 + b*512 + t ; audio nodes: n = 32768 + b*1024 + ta
// ---------------------------------------------------------------------------
#define NNODES 49152

typedef __half half_t;

// Scratch (device globals)
__device__ half_t g_hh[(size_t)NNODES * 1024];    // GEMM output (fp16)
__device__ half_t g_a0[(size_t)NNODES * 1024];    // activations (ping)
__device__ half_t g_a1[(size_t)NNODES * 1024];    // activations (pong)
__device__ half_t g_wh[3014656];                  // weights fp16
__device__ float  g_pas8[NNODES * 8];
__device__ float  g_pad8[NNODES * 8];
__device__ float  g_part[16 * 256];               // per-batch accumulators

struct Ptr5 { const float* p[5]; };

// ---------------------------------------------------------------------------
// helpers
// ---------------------------------------------------------------------------
__device__ __forceinline__ uint32_t smem_u32(const void* p) {
    uint32_t a;
    asm("{ .reg .u64 t; cvta.to.shared.u64 t, %1; cvt.u32.u64 %0, t; }" : "=r"(a) : "l"(p));
    return a;
}
__device__ __forceinline__ uint32_t sw_off(int row, int c16) {
    int p = row >> 1;
    int c = ((row & 1) * 4 + c16) ^ (p & 7);
    return (uint32_t)(p * 128 + (c << 4));
}
__device__ __forceinline__ void ldsm_x4(uint32_t r[4], uint32_t addr) {
    asm volatile("ldmatrix.sync.aligned.m8n8.x4.shared.b16 {%0,%1,%2,%3}, [%4];"
                 : "=r"(r[0]), "=r"(r[1]), "=r"(r[2]), "=r"(r[3]) : "r"(addr));
}
__device__ __forceinline__ void mma_f16(float d[4], const uint32_t a[4],
                                        uint32_t b0, uint32_t b1) {
    asm volatile(
        "mma.sync.aligned.m16n8k16.row.col.f32.f16.f16.f32 "
        "{%0,%1,%2,%3}, {%4,%5,%6,%7}, {%8,%9}, {%0,%1,%2,%3};"
        : "+f"(d[0]), "+f"(d[1]), "+f"(d[2]), "+f"(d[3])
        : "r"(a[0]), "r"(a[1]), "r"(a[2]), "r"(a[3]), "r"(b0), "r"(b1));
}
__device__ __forceinline__ void cpa16(uint32_t sm, const void* g) {
    asm volatile("cp.async.cg.shared.global [%0], [%1], 16;" :: "r"(sm), "l"(g));
}
#define CP_COMMIT() asm volatile("cp.async.commit_group;" ::: "memory")

__device__ __forceinline__ float4 ld_h4(const half_t* p) {
    uint2 u = *(const uint2*)p;
    __half2 a = *reinterpret_cast<__half2*>(&u.x);
    __half2 b = *reinterpret_cast<__half2*>(&u.y);
    float2 fa = __half22float2(a), fb = __half22float2(b);
    return make_float4(fa.x, fa.y, fb.x, fb.y);
}
__device__ __forceinline__ void st_h4(half_t* P, size_t idx, float4 o) {
    __half2 h0 = __floats2half2_rn(o.x, o.y), h1 = __floats2half2_rn(o.z, o.w);
    uint2 u;
    u.x = *reinterpret_cast<uint32_t*>(&h0);
    u.y = *reinterpret_cast<uint32_t*>(&h1);
    *(uint2*)(P + idx) = u;
}
__device__ __forceinline__ uint4 pack8h(float4 a, float4 b) {
    __half2 h0 = __floats2half2_rn(a.x, a.y), h1 = __floats2half2_rn(a.z, a.w);
    __half2 h2 = __floats2half2_rn(b.x, b.y), h3 = __floats2half2_rn(b.z, b.w);
    uint4 u;
    u.x = *reinterpret_cast<uint32_t*>(&h0);
    u.y = *reinterpret_cast<uint32_t*>(&h1);
    u.z = *reinterpret_cast<uint32_t*>(&h2);
    u.w = *reinterpret_cast<uint32_t*>(&h3);
    return u;
}

// ---------------------------------------------------------------------------
// prep_w: weight transpose->fp16 (2944 blocks) + part zeroing (block 2944)
// ---------------------------------------------------------------------------
__device__ void tsp_block_h(const float* __restrict__ in, half_t* __restrict__ oh,
                            int R, int C, int gx, int gy, float (*tile)[33])
{
    int tx = threadIdx.x & 31, ty = threadIdx.x >> 5;
    int c0 = gx * 32, r0 = gy * 32;
    for (int i = ty; i < 32; i += 8)
        tile[i][tx] = in[(size_t)(r0 + i) * C + c0 + tx];
    __syncthreads();
    for (int i = ty; i < 32; i += 8)
        oh[(size_t)(c0 + i) * R + r0 + tx] = __float2half_rn(tile[tx][i]);
}

__global__ __launch_bounds__(256) void prep_w_kernel(
    Ptr5 wP, const float* __restrict__ W0, const float* __restrict__ W1,
    const float* __restrict__ W2, half_t* __restrict__ wh, float* __restrict__ part)
{
    __shared__ float tile[32][33];
    const size_t OFF_W0 = 5 * 131072;
    const size_t OFF_W1 = OFF_W0 + 262144;
    const size_t OFF_W2 = OFF_W1 + 1048576;
    int bid = blockIdx.x;
    if (bid == 2944) {
        for (int i = threadIdx.x; i < 16 * 256; i += 256) part[i] = 0.f;
        return;
    }
    if (bid < 640) {
        int i = bid >> 7, rem = bid & 127;
        tsp_block_h(wP.p[i], wh + (size_t)i * 131072, 512, 256, rem & 7, rem >> 3, tile);
    } else if (bid < 896) {
        int rem = bid - 640;
        tsp_block_h(W0, wh + OFF_W0, 256, 1024, rem & 31, rem >> 5, tile);
    } else if (bid < 1920) {
        int rem = bid - 896;
        tsp_block_h(W1, wh + OFF_W1, 1024, 1024, rem & 31, rem >> 5, tile);
    } else {
        int rem = bid - 1920;
        tsp_block_h(W2, wh + OFF_W2, 1024, 1024, rem & 31, rem >> 5, tile);
    }
}

// ---------------------------------------------------------------------------
// fp16 GEMM (proven config + B-fragment software pipeline):
// C = A @ B^T (+bias), fp32 accumulate.
// CTA 128x128, 8 warps (4m x 2n), warp 32x64, K-chunk 32, 6-stage cp.async,
// 2 CTAs/SM. AF32=1: A read fp32 (segmented inputs) + in-register convert.
// Fused alpha dots -> pas8/pad8.
// ---------------------------------------------------------------------------
#define STAGE_BYTES 16384
#define NSTAGE 6
#define GEMM_DSMEM (NSTAGE * STAGE_BYTES + 128)

extern __shared__ char dynsm[];

template<int AF32>
__global__ __launch_bounds__(256, 2) void mma_gemm_t(
    const half_t* __restrict__ A, Ptr5 ainp,
    const half_t* __restrict__ B,
    long bseg_stride, int nseg, Ptr5 pb,
    half_t* __restrict__ Ch,
    const float* __restrict__ a_s, const float* __restrict__ a_d,
    float* __restrict__ pas8, float* __restrict__ pad8,
    int M, int N, int K)
{
    char* smp = (char*)(((uintptr_t)dynsm + 127) & ~(uintptr_t)127);
    const uint32_t sb = smem_u32(smp);

    const int tid = threadIdx.x, wid = tid >> 5, lane = tid & 31;
    const int bx = blockIdx.x, by = blockIdx.y;
    const int m0 = (wid & 3) * 32, n0 = (wid >> 2) * 64;

    int seg = 0;
    if (nseg > 1) { seg = (by * 128) >> 13; if (seg > 4) seg = 4; }
    const half_t* Bs = B + (size_t)seg * bseg_stride;

    __shared__ float sbias[128], sas[128], sad[128];
    __shared__ float sredS[8][32], sredD[8][32];
    if (tid < 128) {
        sbias[tid] = pb.p[0] ? pb.p[seg][bx * 128 + tid] : 0.f;
        if (a_s) { sas[tid] = a_s[bx * 128 + tid]; sad[tid] = a_d[bx * 128 + tid]; }
    }

    const int r_ = tid >> 2, q_ = tid & 3;
    const uint32_t so0 = sw_off(r_, q_), so1 = sw_off(r_ + 64, q_);
    const size_t rs = (size_t)64 * K;

    const half_t* gA = nullptr;
    const float* gA32 = nullptr;
    if (AF32) {
        int segstart = (seg < 4) ? seg * 8192 : 32768;
        gA32 = ainp.p[seg] + (size_t)(by * 128 + r_ - segstart) * K + q_ * 8;
    } else {
        gA = A + (size_t)(by * 128 + r_) * K + q_ * 8;
    }
    const half_t* gB = Bs + (size_t)(bx * 128 + r_) * K + q_ * 8;

    const int nch = K / 32;

    auto load_chunk_B = [&](int ck) {
        const uint32_t st = sb + (ck % NSTAGE) * STAGE_BYTES;
        const int kb = ck * 32;
        if (!AF32) {
            cpa16(st + so0,        gA + kb);
            cpa16(st + so1,        gA + rs + kb);
        }
        cpa16(st + 8192 + so0, gB + kb);
        cpa16(st + 8192 + so1, gB + rs + kb);
        CP_COMMIT();
    };

    float4 ar[2][2];
    auto ldg_A32 = [&](int ck) {
        const int kb = ck * 32;
        ar[0][0] = *(const float4*)(gA32 + kb);
        ar[0][1] = *(const float4*)(gA32 + kb + 4);
        ar[1][0] = *(const float4*)(gA32 + rs + kb);
        ar[1][1] = *(const float4*)(gA32 + rs + kb + 4);
    };

    float acc[2][8][4];
#pragma unroll
    for (int mt = 0; mt < 2; mt++)
#pragma unroll
        for (int nt = 0; nt < 8; nt++)
#pragma unroll
            for (int k = 0; k < 4; k++) acc[mt][nt][k] = 0.f;

#pragma unroll
    for (int pc = 0; pc < 5; pc++)
        if (pc < nch) load_chunk_B(pc);
    if (AF32) ldg_A32(0);

    const int tile = lane >> 3, rit = lane & 7;
    const int brow = n0 + (tile >> 1) * 8 + rit;   // base row for B fragments

    for (int c = 0; c < nch; c++) {
        if (AF32) {
            char* stg = smp + (c % NSTAGE) * STAGE_BYTES;
            *(uint4*)(stg + so0) = pack8h(ar[0][0], ar[0][1]);
            *(uint4*)(stg + so1) = pack8h(ar[1][0], ar[1][1]);
        }
        const int rem = nch - 1 - c;
        if (rem >= 4)      asm volatile("cp.async.wait_group 4;" ::: "memory");
        else if (rem == 3) asm volatile("cp.async.wait_group 3;" ::: "memory");
        else if (rem == 2) asm volatile("cp.async.wait_group 2;" ::: "memory");
        else if (rem == 1) asm volatile("cp.async.wait_group 1;" ::: "memory");
        else               asm volatile("cp.async.wait_group 0;" ::: "memory");
        __syncthreads();
        if (c + 5 < nch) load_chunk_B(c + 5);
        if (AF32 && c + 1 < nch) ldg_A32(c + 1);

        const uint32_t sbase = sb + (c % NSTAGE) * STAGE_BYTES;
#pragma unroll
        for (int ks = 0; ks < 2; ks++) {
            uint32_t af[2][4];
#pragma unroll
            for (int mt = 0; mt < 2; mt++) {
                int row = m0 + mt * 16 + (tile & 1) * 8 + rit;
                ldsm_x4(af[mt], sbase + sw_off(row, ks * 2 + (tile >> 1)));
            }
            // B fragments: double-buffered, one load ahead of consumption
            uint32_t bh[2][4];
            ldsm_x4(bh[0], sbase + 8192 + sw_off(brow, ks * 2 + (tile & 1)));
#pragma unroll
            for (int p = 0; p < 4; p++) {
                const int cur = p & 1;
                if (p < 3)
                    ldsm_x4(bh[cur ^ 1],
                            sbase + 8192 + sw_off(brow + (p + 1) * 16, ks * 2 + (tile & 1)));
#pragma unroll
                for (int mt = 0; mt < 2; mt++) {
                    mma_f16(acc[mt][p * 2 + 0], af[mt], bh[cur][0], bh[cur][1]);
                    mma_f16(acc[mt][p * 2 + 1], af[mt], bh[cur][2], bh[cur][3]);
                }
            }
        }
        if (AF32) __syncthreads();
    }

    // epilogue: bias + fp16 store
#pragma unroll
    for (int mt = 0; mt < 2; mt++) {
        const int r = by * 128 + m0 + mt * 16 + (lane >> 2);
#pragma unroll
        for (int nt = 0; nt < 8; nt++) {
            const int cl = n0 + nt * 8 + (lane & 3) * 2;
            const int cg = bx * 128 + cl;
            float v0 = acc[mt][nt][0] + sbias[cl];
            float v1 = acc[mt][nt][1] + sbias[cl + 1];
            float v2 = acc[mt][nt][2] + sbias[cl];
            float v3 = acc[mt][nt][3] + sbias[cl + 1];
            *(__half2*)(Ch + (size_t)r * N + cg) = __floats2half2_rn(v0, v1);
            *(__half2*)(Ch + (size_t)(r + 8) * N + cg) = __floats2half2_rn(v2, v3);
        }
    }

    if (a_s) {
        float sp[2][2] = {{0.f, 0.f}, {0.f, 0.f}};
        float dp[2][2] = {{0.f, 0.f}, {0.f, 0.f}};
#pragma unroll
        for (int mt = 0; mt < 2; mt++)
#pragma unroll
            for (int nt = 0; nt < 8; nt++) {
                const int cl = n0 + nt * 8 + (lane & 3) * 2;
                sp[mt][0] += acc[mt][nt][0] * sas[cl] + acc[mt][nt][1] * sas[cl + 1];
                dp[mt][0] += acc[mt][nt][0] * sad[cl] + acc[mt][nt][1] * sad[cl + 1];
                sp[mt][1] += acc[mt][nt][2] * sas[cl] + acc[mt][nt][3] * sas[cl + 1];
                dp[mt][1] += acc[mt][nt][2] * sad[cl] + acc[mt][nt][3] * sad[cl + 1];
            }
#pragma unroll
        for (int mt = 0; mt < 2; mt++)
#pragma unroll
            for (int h8 = 0; h8 < 2; h8++) {
                float s = sp[mt][h8], d = dp[mt][h8];
                s += __shfl_xor_sync(0xffffffffu, s, 1);
                s += __shfl_xor_sync(0xffffffffu, s, 2);
                d += __shfl_xor_sync(0xffffffffu, d, 1);
                d += __shfl_xor_sync(0xffffffffu, d, 2);
                if ((lane & 3) == 0) {
                    int rw = mt * 16 + h8 * 8 + (lane >> 2);
                    sredS[wid][rw] = s;
                    sredD[wid][rw] = d;
                }
            }
        __syncthreads();
        if (wid < 4) {
            float s = sredS[wid][lane] + sredS[wid + 4][lane];
            float d = sredD[wid][lane] + sredD[wid + 4][lane];
            int n = by * 128 + wid * 32 + lane;
            pas8[n * 8 + bx] = s;
            pad8[n * 8 + bx] = d;
        }
    }
}

// ---------------------------------------------------------------------------
// Alpha helpers
// ---------------------------------------------------------------------------
__device__ __forceinline__ float rd_as(const float* p8, int n, int hd) {
    return p8[n * 8 + 2 * hd] + p8[n * 8 + 2 * hd + 1];
}

// ---------------------------------------------------------------------------
// Strip aggregation (concat layers).
// grid = 4096 (region strips of 2 timesteps) + 8192 (audio even/odd pairs).
// ---------------------------------------------------------------------------
__global__ __launch_bounds__(256, 4) void agg_strip_kernel(
    const half_t* __restrict__ h, const float* __restrict__ pas8,
    const float* __restrict__ pad8, const float* __restrict__ bias,
    half_t* __restrict__ outA)
{
    const int bid = blockIdx.x, tid = threadIdx.x;
    if (bid < 4096) {
        const int bt0 = bid * 2;
        const int t0 = bt0 & 511;
        __shared__ float wc[2][4][4][4];
        __shared__ float wp[2][4][4];
        if (tid < 32) {
            int tt = tid >> 4, j = (tid >> 2) & 3, hd = tid & 3;
            int bt = bt0 + tt, t = t0 + tt;
            int n = j * 8192 + bt;
            float adv = rd_as(pad8, n, hd);
            float e[5]; int ei[3]; int cnt = 0;
            for (int i = 0; i < 4; i++)
                if (i != j) { e[cnt] = rd_as(pas8, i * 8192 + bt, hd) + adv; ei[cnt] = i; cnt++; }
            int prevIdx = -1;
            if (t > 0) { e[cnt] = rd_as(pas8, n - 1, hd) + adv; prevIdx = cnt; cnt++; }
            int selfIdx = cnt; e[cnt] = rd_as(pas8, n, hd) + adv; cnt++;
            float m = -1e30f;
            for (int k = 0; k < cnt; k++) { float v = e[k]; v = v >= 0.f ? v : 0.2f * v; e[k] = v; m = fmaxf(m, v); }
            float den = 0.f;
            for (int k = 0; k < cnt; k++) { e[k] = __expf(e[k] - m); den += e[k]; }
            float inv = 1.f / (den + 1e-16f);
            float w4[4] = {0.f, 0.f, 0.f, 0.f};
            for (int k = 0; k < 3; k++) w4[ei[k]] = e[k] * inv;
            w4[j] = e[selfIdx] * inv;
            for (int i = 0; i < 4; i++) wc[tt][j][hd][i] = w4[i];
            wp[tt][j][hd] = (prevIdx >= 0) ? e[prevIdx] * inv : 0.f;
        }
        __syncthreads();
        const int c4 = tid * 4;
        const int hd = c4 >> 8;
        float4 bb = *(const float4*)&bias[c4];
        float4 prv[4];
        if (t0 > 0) {
#pragma unroll
            for (int i = 0; i < 4; i++)
                prv[i] = ld_h4(h + (size_t)(i * 8192 + bt0 - 1) * 1024 + c4);
        } else {
#pragma unroll
            for (int i = 0; i < 4; i++) prv[i] = make_float4(0.f, 0.f, 0.f, 0.f);
        }
#pragma unroll
        for (int tt = 0; tt < 2; tt++) {
            const int bt = bt0 + tt;
            float4 cur[4];
#pragma unroll
            for (int i = 0; i < 4; i++)
                cur[i] = ld_h4(h + (size_t)(i * 8192 + bt) * 1024 + c4);
#pragma unroll
            for (int j = 0; j < 4; j++) {
                float w0 = wc[tt][j][hd][0], w1 = wc[tt][j][hd][1];
                float w2 = wc[tt][j][hd][2], w3 = wc[tt][j][hd][3], wpp = wp[tt][j][hd];
                float4 o;
                o.x = w0 * cur[0].x + w1 * cur[1].x + w2 * cur[2].x + w3 * cur[3].x + wpp * prv[j].x + bb.x;
                o.y = w0 * cur[0].y + w1 * cur[1].y + w2 * cur[2].y + w3 * cur[3].y + wpp * prv[j].y + bb.y;
                o.z = w0 * cur[0].z + w1 * cur[1].z + w2 * cur[2].z + w3 * cur[3].z + wpp * prv[j].z + bb.z;
                o.w = w0 * cur[0].w + w1 * cur[1].w + w2 * cur[2].w + w3 * cur[3].w + wpp * prv[j].w + bb.w;
                st_h4(outA, (size_t)(j * 8192 + bt) * 1024 + c4, o);
            }
#pragma unroll
            for (int i = 0; i < 4; i++) prv[i] = cur[i];
        }
    } else {
        const int ap = bid - 4096;
        const int b = ap >> 9, tp = ap & 511;
        const int n0 = 32768 + b * 1024 + 2 * tp;
        const int bt = b * 512 + tp;
        __shared__ float al[4][3];
        if (tid < 4) {
            int hd = tid;
            int srcs[3] = { 8192 + bt, 16384 + bt, n0 };
            float adv = rd_as(pad8, n0, hd);
            float e[3], m = -1e30f;
            for (int k = 0; k < 3; k++) {
                float v = rd_as(pas8, srcs[k], hd) + adv;
                v = v >= 0.f ? v : 0.2f * v;
                e[k] = v; m = fmaxf(m, v);
            }
            float den = 0.f;
            for (int k = 0; k < 3; k++) { e[k] = __expf(e[k] - m); den += e[k]; }
            float inv = 1.f / (den + 1e-16f);
            for (int k = 0; k < 3; k++) al[hd][k] = e[k] * inv;
        }
        __syncthreads();
        const int c4 = tid * 4;
        const int hd = c4 >> 8;
        float4 bb = *(const float4*)&bias[c4];
        float4 vL = ld_h4(h + (size_t)(8192 + bt) * 1024 + c4);
        float4 vR = ld_h4(h + (size_t)(16384 + bt) * 1024 + c4);
        float4 vS = ld_h4(h + (size_t)n0 * 1024 + c4);
        float w0 = al[hd][0], w1 = al[hd][1], w2 = al[hd][2];
        float4 o;
        o.x = w0 * vL.x + w1 * vR.x + w2 * vS.x + bb.x;
        o.y = w0 * vL.y + w1 * vR.y + w2 * vS.y + bb.y;
        o.z = w0 * vL.z + w1 * vR.z + w2 * vS.z + bb.z;
        o.w = w0 * vL.w + w1 * vR.w + w2 * vS.w + bb.w;
        st_h4(outA, (size_t)n0 * 1024 + c4, o);
        float4 vO = ld_h4(h + (size_t)(n0 + 1) * 1024 + c4);
        float4 o2 = make_float4(vO.x + bb.x, vO.y + bb.y, vO.z + bb.z, vO.w + bb.w);
        st_h4(outA, (size_t)(n0 + 1) * 1024 + c4, o2);
    }
}

// ---------------------------------------------------------------------------
// Fused: head-mean aggregation (layer 2) + LayerNorm + per-batch mean partial.
// ---------------------------------------------------------------------------
__device__ __forceinline__ void ln_atomic_row(
    float o, int tid, int warp, int lane, float (*red)[8],
    const float* ln_g, const float* ln_b, float* part, int b_out)
{
    float s = o, q = o * o;
#pragma unroll
    for (int off = 16; off; off >>= 1) {
        s += __shfl_xor_sync(0xffffffffu, s, off);
        q += __shfl_xor_sync(0xffffffffu, q, off);
    }
    if (lane == 0) { red[0][warp] = s; red[1][warp] = q; }
    __syncthreads();
    float ts = 0.f, tq = 0.f;
#pragma unroll
    for (int w = 0; w < 8; w++) { ts += red[0][w]; tq += red[1][w]; }
    float mu = ts * (1.f / 256.f);
    float var = tq * (1.f / 256.f) - mu * mu;
    float rstd = rsqrtf(var + 1e-5f);
    float v = (o - mu) * rstd * ln_g[tid] + ln_b[tid];
    atomicAdd(&part[b_out * 256 + tid], v);
    __syncthreads();
}

__global__ __launch_bounds__(256, 4) void agg_mean_ln_kernel(
    const half_t* __restrict__ h, const float* __restrict__ pas8,
    const float* __restrict__ pad8, const float* __restrict__ bias,
    const float* __restrict__ ln_g, const float* __restrict__ ln_b,
    float* __restrict__ part)
{
    const int bid = blockIdx.x, tid = threadIdx.x;
    const int warp = tid >> 5, lane = tid & 31;
    __shared__ float red[2][8];
    if (bid < 8192) {
        const int bt = bid, t = bt & 511;
        __shared__ float wcur[4][4][4];
        __shared__ float wprev[4][4];
        if (tid < 16) {
            int j = tid >> 2, hd = tid & 3;
            int n = j * 8192 + bt;
            float adv = rd_as(pad8, n, hd);
            float e[5]; int ei[3]; int cnt = 0;
            for (int i = 0; i < 4; i++)
                if (i != j) { e[cnt] = rd_as(pas8, i * 8192 + bt, hd) + adv; ei[cnt] = i; cnt++; }
            int prevIdx = -1;
            if (t > 0) { e[cnt] = rd_as(pas8, n - 1, hd) + adv; prevIdx = cnt; cnt++; }
            int selfIdx = cnt; e[cnt] = rd_as(pas8, n, hd) + adv; cnt++;
            float m = -1e30f;
            for (int k = 0; k < cnt; k++) { float v = e[k]; v = v >= 0.f ? v : 0.2f * v; e[k] = v; m = fmaxf(m, v); }
            float den = 0.f;
            for (int k = 0; k < cnt; k++) { e[k] = __expf(e[k] - m); den += e[k]; }
            float inv = 1.f / (den + 1e-16f);
            float wcv[4] = {0.f, 0.f, 0.f, 0.f};
            for (int k = 0; k < 3; k++) wcv[ei[k]] = e[k] * inv;
            wcv[j] = e[selfIdx] * inv;
            for (int i = 0; i < 4; i++) wcur[j][hd][i] = wcv[i];
            wprev[j][hd] = (prevIdx >= 0) ? e[prevIdx] * inv : 0.f;
        }
        __syncthreads();
        __shared__ float sm[4][4][256];
        const int hd = tid >> 6, cb = (tid & 63) * 4;
        float4 cur[4], prv[4];
#pragma unroll
        for (int i = 0; i < 4; i++)
            cur[i] = ld_h4(h + (size_t)(i * 8192 + bt) * 1024 + hd * 256 + cb);
        if (t > 0) {
#pragma unroll
            for (int i = 0; i < 4; i++)
                prv[i] = ld_h4(h + (size_t)(i * 8192 + bt - 1) * 1024 + hd * 256 + cb);
        } else {
#pragma unroll
            for (int i = 0; i < 4; i++) prv[i] = make_float4(0.f, 0.f, 0.f, 0.f);
        }
#pragma unroll
        for (int j = 0; j < 4; j++) {
            float w0 = wcur[j][hd][0], w1 = wcur[j][hd][1];
            float w2 = wcur[j][hd][2], w3 = wcur[j][hd][3], wpp = wprev[j][hd];
            float4 o;
            o.x = w0 * cur[0].x + w1 * cur[1].x + w2 * cur[2].x + w3 * cur[3].x + wpp * prv[j].x;
            o.y = w0 * cur[0].y + w1 * cur[1].y + w2 * cur[2].y + w3 * cur[3].y + wpp * prv[j].y;
            o.z = w0 * cur[0].z + w1 * cur[1].z + w2 * cur[2].z + w3 * cur[3].z + wpp * prv[j].z;
            o.w = w0 * cur[0].w + w1 * cur[1].w + w2 * cur[2].w + w3 * cur[3].w + wpp * prv[j].w;
            *(float4*)&sm[hd][j][cb] = o;
        }
        __syncthreads();
#pragma unroll
        for (int j = 0; j < 4; j++) {
            float o = (sm[0][j][tid] + sm[1][j][tid] + sm[2][j][tid] + sm[3][j][tid]) * 0.25f
                    + bias[tid];
            int n = j * 8192 + bt;
            ln_atomic_row(o, tid, warp, lane, red, ln_g, ln_b, part, n / 3072);
        }
    } else {
        const int ap = bid - 8192;
        const int b = ap >> 9, tp = ap & 511;
        const int n0 = 32768 + b * 1024 + 2 * tp;
        const int bt = b * 512 + tp;
        __shared__ float al[4][3];
        if (tid < 4) {
            int hd = tid;
            int srcs[3] = { 8192 + bt, 16384 + bt, n0 };
            float adv = rd_as(pad8, n0, hd);
            float e[3], m = -1e30f;
            for (int k = 0; k < 3; k++) {
                float v = rd_as(pas8, srcs[k], hd) + adv;
                v = v >= 0.f ? v : 0.2f * v;
                e[k] = v; m = fmaxf(m, v);
            }
            float den = 0.f;
            for (int k = 0; k < 3; k++) { e[k] = __expf(e[k] - m); den += e[k]; }
            float inv = 1.f / (den + 1e-16f);
            for (int k = 0; k < 3; k++) al[hd][k] = e[k] * inv;
        }
        __syncthreads();
        __shared__ float sm2[2][4][256];
        const int hd = tid >> 6, cb = (tid & 63) * 4;
        {
            float4 vL = ld_h4(h + (size_t)(8192 + bt) * 1024 + hd * 256 + cb);
            float4 vR = ld_h4(h + (size_t)(16384 + bt) * 1024 + hd * 256 + cb);
            float4 vS = ld_h4(h + (size_t)n0 * 1024 + hd * 256 + cb);
            float w0 = al[hd][0], w1 = al[hd][1], w2 = al[hd][2];
            float4 o;
            o.x = w0 * vL.x + w1 * vR.x + w2 * vS.x;
            o.y = w0 * vL.y + w1 * vR.y + w2 * vS.y;
            o.z = w0 * vL.z + w1 * vR.z + w2 * vS.z;
            o.w = w0 * vL.w + w1 * vR.w + w2 * vS.w;
            *(float4*)&sm2[0][hd][cb] = o;
        }
        {
            float4 vO = ld_h4(h + (size_t)(n0 + 1) * 1024 + hd * 256 + cb);
            *(float4*)&sm2[1][hd][cb] = vO;
        }
        __syncthreads();
#pragma unroll
        for (int e = 0; e < 2; e++) {
            float o = (sm2[e][0][tid] + sm2[e][1][tid] + sm2[e][2][tid] + sm2[e][3][tid]) * 0.25f
                    + bias[tid];
            int n = n0 + e;
            ln_atomic_row(o, tid, warp, lane, red, ln_g, ln_b, part, n / 3072);
        }
    }
}

__global__ void reduce_out_kernel(const float* __restrict__ part, float* __restrict__ out)
{
    int b = blockIdx.x, c = threadIdx.x;
    out[b * 256 + c] = part[b * 256 + c] * (1.f / 3072.f);
}

// ---------------------------------------------------------------------------
// Launch
// ---------------------------------------------------------------------------
extern "C" void kernel_launch(void* const* d_in, const int* in_sizes, int n_in,
                              void* d_out, int out_size)
{
    Ptr5 inp = {{ (const float*)d_in[0], (const float*)d_in[1], (const float*)d_in[2],
                  (const float*)d_in[3], (const float*)d_in[4] }};
    Ptr5 wP  = {{ (const float*)d_in[5], (const float*)d_in[7], (const float*)d_in[9],
                  (const float*)d_in[11], (const float*)d_in[13] }};
    Ptr5 projb = {{ (const float*)d_in[6], (const float*)d_in[8], (const float*)d_in[10],
                    (const float*)d_in[12], (const float*)d_in[14] }};
    Ptr5 nob = {{ nullptr, nullptr, nullptr, nullptr, nullptr }};
    const float* W0 = (const float*)d_in[15];
    const float* as0 = (const float*)d_in[16];
    const float* ad0 = (const float*)d_in[17];
    const float* bias0 = (const float*)d_in[18];
    const float* W1 = (const float*)d_in[19];
    const float* as1 = (const float*)d_in[20];
    const float* ad1 = (const float*)d_in[21];
    const float* bias1 = (const float*)d_in[22];
    const float* W2 = (const float*)d_in[23];
    const float* as2 = (const float*)d_in[24];
    const float* ad2 = (const float*)d_in[25];
    const float* bias2 = (const float*)d_in[26];
    const float* ln_g = (const float*)d_in[27];
    const float* ln_b = (const float*)d_in[28];
    float* out = (float*)d_out;

    float *pas8, *pad8, *part;
    half_t *hh, *a0, *a1, *wh;
    cudaGetSymbolAddress((void**)&hh, g_hh);
    cudaGetSymbolAddress((void**)&pas8, g_pas8);
    cudaGetSymbolAddress((void**)&pad8, g_pad8);
    cudaGetSymbolAddress((void**)&part, g_part);
    cudaGetSymbolAddress((void**)&a0, g_a0);
    cudaGetSymbolAddress((void**)&a1, g_a1);
    cudaGetSymbolAddress((void**)&wh, g_wh);

    cudaFuncSetAttribute(mma_gemm_t<0>, cudaFuncAttributeMaxDynamicSharedMemorySize, GEMM_DSMEM);
    cudaFuncSetAttribute(mma_gemm_t<1>, cudaFuncAttributeMaxDynamicSharedMemorySize, GEMM_DSMEM);

    const size_t OFF_PROJ = 0;
    const size_t OFF_W0 = 5 * 131072;
    const size_t OFF_W1 = OFF_W0 + 262144;
    const size_t OFF_W2 = OFF_W1 + 1048576;

    // launch 0: weight prep + part zeroing
    prep_w_kernel<<<2945, 256>>>(wP, W0, W1, W2, wh, part);

    // launch 1: projections (fp32 A fused convert, batched 5 segments) -> a1
    mma_gemm_t<1><<<dim3(2, 384), 256, GEMM_DSMEM>>>(
        nullptr, inp, wh + OFF_PROJ, 131072, 5, projb,
        a1, nullptr, nullptr, nullptr, nullptr,
        NNODES, 256, 512);

    // launch 2: GAT layer 0 GEMM (K=256)
    mma_gemm_t<0><<<dim3(8, 384), 256, GEMM_DSMEM>>>(
        a1, nob, wh + OFF_W0, 0, 1, nob,
        hh, as0, ad0, pas8, pad8,
        NNODES, 1024, 256);
    // launch 3: aggregate 0
    agg_strip_kernel<<<12288, 256>>>(hh, pas8, pad8, bias0, a0);

    // launch 4: GAT layer 1 GEMM (K=1024)
    mma_gemm_t<0><<<dim3(8, 384), 256, GEMM_DSMEM>>>(
        a0, nob, wh + OFF_W1, 0, 1, nob,
        hh, as1, ad1, pas8, pad8,
        NNODES, 1024, 1024);
    // launch 5: aggregate 1
    agg_strip_kernel<<<12288, 256>>>(hh, pas8, pad8, bias1, a1);

    // launch 6: GAT layer 2 GEMM (K=1024)
    mma_gemm_t<0><<<dim3(8, 384), 256, GEMM_DSMEM>>>(
        a1, nob, wh + OFF_W2, 0, 1, nob,
        hh, as2, ad2, pas8, pad8,
        NNODES, 1024, 1024);
    // launch 7: fused head-mean aggregate + LayerNorm + batch-mean partials
    agg_mean_ln_kernel<<<16384, 256>>>(hh, pas8, pad8, bias2, ln_g, ln_b, part);

    // launch 8: final scale
    reduce_out_kernel<<<16, 256>>>(part, out);
}

// round 17
// speedup vs baseline: 1.4456x; 1.0049x over previous
#include <cuda_runtime.h>
#include <cuda_fp16.h>
#include <math.h>
#include <cstdint>

// ---------------------------------------------------------------------------
// Constants: B=16, T=512, TA=1024, NREG=4, D=512, HID=256, HEADS=4
// Region nodes: n = region*8192 + b*512 + t ; audio nodes: n = 32768 + b*1024 + ta
// h scratch uses INTERLEAVED region rows: hrow(n) = (n&8191)*4 + (n>>13) for
// n < 32768 (4 regions of one (b,t) contiguous); audio rows unchanged.
// ---------------------------------------------------------------------------
#define NNODES 49152

typedef __half half_t;

// Scratch (device globals)
__device__ half_t g_hh[(size_t)NNODES * 1024];    // GEMM output (fp16, interleaved)
__device__ half_t g_a0[(size_t)NNODES * 1024];    // activations (ping, semantic)
__device__ half_t g_a1[(size_t)NNODES * 1024];    // activations (pong, semantic)
__device__ half_t g_wh[3014656];                  // weights fp16
__device__ float  g_pas8[NNODES * 8];
__device__ float  g_pad8[NNODES * 8];
__device__ float  g_part[16 * 256];               // per-batch accumulators

struct Ptr5 { const float* p[5]; };

// ---------------------------------------------------------------------------
// helpers
// ---------------------------------------------------------------------------
__device__ __forceinline__ uint32_t smem_u32(const void* p) {
    uint32_t a;
    asm("{ .reg .u64 t; cvta.to.shared.u64 t, %1; cvt.u32.u64 %0, t; }" : "=r"(a) : "l"(p));
    return a;
}
__device__ __forceinline__ uint32_t sw_off(int row, int c16) {
    int p = row >> 1;
    int c = ((row & 1) * 4 + c16) ^ (p & 7);
    return (uint32_t)(p * 128 + (c << 4));
}
__device__ __forceinline__ void ldsm_x4(uint32_t r[4], uint32_t addr) {
    asm volatile("ldmatrix.sync.aligned.m8n8.x4.shared.b16 {%0,%1,%2,%3}, [%4];"
                 : "=r"(r[0]), "=r"(r[1]), "=r"(r[2]), "=r"(r[3]) : "r"(addr));
}
__device__ __forceinline__ void mma_f16(float d[4], const uint32_t a[4],
                                        uint32_t b0, uint32_t b1) {
    asm volatile(
        "mma.sync.aligned.m16n8k16.row.col.f32.f16.f16.f32 "
        "{%0,%1,%2,%3}, {%4,%5,%6,%7}, {%8,%9}, {%0,%1,%2,%3};"
        : "+f"(d[0]), "+f"(d[1]), "+f"(d[2]), "+f"(d[3])
        : "r"(a[0]), "r"(a[1]), "r"(a[2]), "r"(a[3]), "r"(b0), "r"(b1));
}
__device__ __forceinline__ void cpa16(uint32_t sm, const void* g) {
    asm volatile("cp.async.cg.shared.global [%0], [%1], 16;" :: "r"(sm), "l"(g));
}
#define CP_COMMIT() asm volatile("cp.async.commit_group;" ::: "memory")

__device__ __forceinline__ float4 ld_h4(const half_t* p) {
    uint2 u = *(const uint2*)p;
    __half2 a = *reinterpret_cast<__half2*>(&u.x);
    __half2 b = *reinterpret_cast<__half2*>(&u.y);
    float2 fa = __half22float2(a), fb = __half22float2(b);
    return make_float4(fa.x, fa.y, fb.x, fb.y);
}
__device__ __forceinline__ void st_h4(half_t* P, size_t idx, float4 o) {
    __half2 h0 = __floats2half2_rn(o.x, o.y), h1 = __floats2half2_rn(o.z, o.w);
    uint2 u;
    u.x = *reinterpret_cast<uint32_t*>(&h0);
    u.y = *reinterpret_cast<uint32_t*>(&h1);
    *(uint2*)(P + idx) = u;
}
__device__ __forceinline__ uint4 pack8h(float4 a, float4 b) {
    __half2 h0 = __floats2half2_rn(a.x, a.y), h1 = __floats2half2_rn(a.z, a.w);
    __half2 h2 = __floats2half2_rn(b.x, b.y), h3 = __floats2half2_rn(b.z, b.w);
    uint4 u;
    u.x = *reinterpret_cast<uint32_t*>(&h0);
    u.y = *reinterpret_cast<uint32_t*>(&h1);
    u.z = *reinterpret_cast<uint32_t*>(&h2);
    u.w = *reinterpret_cast<uint32_t*>(&h3);
    return u;
}

// ---------------------------------------------------------------------------
// prep_w: weight transpose->fp16 (2944 blocks) + part zeroing (block 2944)
// ---------------------------------------------------------------------------
__device__ void tsp_block_h(const float* __restrict__ in, half_t* __restrict__ oh,
                            int R, int C, int gx, int gy, float (*tile)[33])
{
    int tx = threadIdx.x & 31, ty = threadIdx.x >> 5;
    int c0 = gx * 32, r0 = gy * 32;
    for (int i = ty; i < 32; i += 8)
        tile[i][tx] = in[(size_t)(r0 + i) * C + c0 + tx];
    __syncthreads();
    for (int i = ty; i < 32; i += 8)
        oh[(size_t)(c0 + i) * R + r0 + tx] = __float2half_rn(tile[tx][i]);
}

__global__ __launch_bounds__(256) void prep_w_kernel(
    Ptr5 wP, const float* __restrict__ W0, const float* __restrict__ W1,
    const float* __restrict__ W2, half_t* __restrict__ wh, float* __restrict__ part)
{
    __shared__ float tile[32][33];
    const size_t OFF_W0 = 5 * 131072;
    const size_t OFF_W1 = OFF_W0 + 262144;
    const size_t OFF_W2 = OFF_W1 + 1048576;
    int bid = blockIdx.x;
    if (bid == 2944) {
        for (int i = threadIdx.x; i < 16 * 256; i += 256) part[i] = 0.f;
        return;
    }
    if (bid < 640) {
        int i = bid >> 7, rem = bid & 127;
        tsp_block_h(wP.p[i], wh + (size_t)i * 131072, 512, 256, rem & 7, rem >> 3, tile);
    } else if (bid < 896) {
        int rem = bid - 640;
        tsp_block_h(W0, wh + OFF_W0, 256, 1024, rem & 31, rem >> 5, tile);
    } else if (bid < 1920) {
        int rem = bid - 896;
        tsp_block_h(W1, wh + OFF_W1, 1024, 1024, rem & 31, rem >> 5, tile);
    } else {
        int rem = bid - 1920;
        tsp_block_h(W2, wh + OFF_W2, 1024, 1024, rem & 31, rem >> 5, tile);
    }
}

// ---------------------------------------------------------------------------
// fp16 GEMM (proven config + B-fragment software pipeline):
// C = A @ B^T (+bias), fp32 accumulate.
// CTA 128x128, 8 warps (4m x 2n), warp 32x64, K-chunk 32, 6-stage cp.async,
// 2 CTAs/SM. AF32=1: A read fp32 + in-register convert.
// permC=1: C rows written through hrow() interleave.
// Fused alpha dots -> pas8/pad8 (semantic n).
// ---------------------------------------------------------------------------
#define STAGE_BYTES 16384
#define NSTAGE 6
#define GEMM_DSMEM (NSTAGE * STAGE_BYTES + 128)

extern __shared__ char dynsm[];

template<int AF32>
__global__ __launch_bounds__(256, 2) void mma_gemm_t(
    const half_t* __restrict__ A, Ptr5 ainp,
    const half_t* __restrict__ B,
    long bseg_stride, int nseg, Ptr5 pb, int permC,
    half_t* __restrict__ Ch,
    const float* __restrict__ a_s, const float* __restrict__ a_d,
    float* __restrict__ pas8, float* __restrict__ pad8,
    int M, int N, int K)
{
    char* smp = (char*)(((uintptr_t)dynsm + 127) & ~(uintptr_t)127);
    const uint32_t sb = smem_u32(smp);

    const int tid = threadIdx.x, wid = tid >> 5, lane = tid & 31;
    const int bx = blockIdx.x, by = blockIdx.y;
    const int m0 = (wid & 3) * 32, n0 = (wid >> 2) * 64;

    int seg = 0;
    if (nseg > 1) { seg = (by * 128) >> 13; if (seg > 4) seg = 4; }
    const half_t* Bs = B + (size_t)seg * bseg_stride;

    __shared__ float sbias[128], sas[128], sad[128];
    __shared__ float sredS[8][32], sredD[8][32];
    if (tid < 128) {
        sbias[tid] = pb.p[0] ? pb.p[seg][bx * 128 + tid] : 0.f;
        if (a_s) { sas[tid] = a_s[bx * 128 + tid]; sad[tid] = a_d[bx * 128 + tid]; }
    }

    const int r_ = tid >> 2, q_ = tid & 3;
    const uint32_t so0 = sw_off(r_, q_), so1 = sw_off(r_ + 64, q_);
    const size_t rs = (size_t)64 * K;

    const half_t* gA = nullptr;
    const float* gA32 = nullptr;
    if (AF32) {
        int segstart = (seg < 4) ? seg * 8192 : 32768;
        gA32 = ainp.p[seg] + (size_t)(by * 128 + r_ - segstart) * K + q_ * 8;
    } else {
        gA = A + (size_t)(by * 128 + r_) * K + q_ * 8;
    }
    const half_t* gB = Bs + (size_t)(bx * 128 + r_) * K + q_ * 8;

    const int nch = K / 32;

    auto load_chunk_B = [&](int ck) {
        const uint32_t st = sb + (ck % NSTAGE) * STAGE_BYTES;
        const int kb = ck * 32;
        if (!AF32) {
            cpa16(st + so0,        gA + kb);
            cpa16(st + so1,        gA + rs + kb);
        }
        cpa16(st + 8192 + so0, gB + kb);
        cpa16(st + 8192 + so1, gB + rs + kb);
        CP_COMMIT();
    };

    float4 ar[2][2];
    auto ldg_A32 = [&](int ck) {
        const int kb = ck * 32;
        ar[0][0] = *(const float4*)(gA32 + kb);
        ar[0][1] = *(const float4*)(gA32 + kb + 4);
        ar[1][0] = *(const float4*)(gA32 + rs + kb);
        ar[1][1] = *(const float4*)(gA32 + rs + kb + 4);
    };

    float acc[2][8][4];
#pragma unroll
    for (int mt = 0; mt < 2; mt++)
#pragma unroll
        for (int nt = 0; nt < 8; nt++)
#pragma unroll
            for (int k = 0; k < 4; k++) acc[mt][nt][k] = 0.f;

#pragma unroll
    for (int pc = 0; pc < 5; pc++)
        if (pc < nch) load_chunk_B(pc);
    if (AF32) ldg_A32(0);

    const int tile = lane >> 3, rit = lane & 7;
    const int brow = n0 + (tile >> 1) * 8 + rit;   // base row for B fragments

    for (int c = 0; c < nch; c++) {
        if (AF32) {
            char* stg = smp + (c % NSTAGE) * STAGE_BYTES;
            *(uint4*)(stg + so0) = pack8h(ar[0][0], ar[0][1]);
            *(uint4*)(stg + so1) = pack8h(ar[1][0], ar[1][1]);
        }
        const int rem = nch - 1 - c;
        if (rem >= 4)      asm volatile("cp.async.wait_group 4;" ::: "memory");
        else if (rem == 3) asm volatile("cp.async.wait_group 3;" ::: "memory");
        else if (rem == 2) asm volatile("cp.async.wait_group 2;" ::: "memory");
        else if (rem == 1) asm volatile("cp.async.wait_group 1;" ::: "memory");
        else               asm volatile("cp.async.wait_group 0;" ::: "memory");
        __syncthreads();
        if (c + 5 < nch) load_chunk_B(c + 5);
        if (AF32 && c + 1 < nch) ldg_A32(c + 1);

        const uint32_t sbase = sb + (c % NSTAGE) * STAGE_BYTES;
#pragma unroll
        for (int ks = 0; ks < 2; ks++) {
            uint32_t af[2][4];
#pragma unroll
            for (int mt = 0; mt < 2; mt++) {
                int row = m0 + mt * 16 + (tile & 1) * 8 + rit;
                ldsm_x4(af[mt], sbase + sw_off(row, ks * 2 + (tile >> 1)));
            }
            uint32_t bh[2][4];
            ldsm_x4(bh[0], sbase + 8192 + sw_off(brow, ks * 2 + (tile & 1)));
#pragma unroll
            for (int p = 0; p < 4; p++) {
                const int cur = p & 1;
                if (p < 3)
                    ldsm_x4(bh[cur ^ 1],
                            sbase + 8192 + sw_off(brow + (p + 1) * 16, ks * 2 + (tile & 1)));
#pragma unroll
                for (int mt = 0; mt < 2; mt++) {
                    mma_f16(acc[mt][p * 2 + 0], af[mt], bh[cur][0], bh[cur][1]);
                    mma_f16(acc[mt][p * 2 + 1], af[mt], bh[cur][2], bh[cur][3]);
                }
            }
        }
        if (AF32) __syncthreads();
    }

    // epilogue: bias + fp16 store (optionally through interleave)
#pragma unroll
    for (int mt = 0; mt < 2; mt++) {
        const int r = by * 128 + m0 + mt * 16 + (lane >> 2);
        size_t pr0, pr1;
        if (permC && r < 32768) {
            pr0 = ((size_t)(r & 8191) << 2) | (uint32_t)(r >> 13);
            pr1 = pr0 + 32;               // perm(r+8) within same region block
        } else {
            pr0 = (size_t)r;
            pr1 = (size_t)r + 8;
        }
#pragma unroll
        for (int nt = 0; nt < 8; nt++) {
            const int cl = n0 + nt * 8 + (lane & 3) * 2;
            const int cg = bx * 128 + cl;
            float v0 = acc[mt][nt][0] + sbias[cl];
            float v1 = acc[mt][nt][1] + sbias[cl + 1];
            float v2 = acc[mt][nt][2] + sbias[cl];
            float v3 = acc[mt][nt][3] + sbias[cl + 1];
            *(__half2*)(Ch + pr0 * N + cg) = __floats2half2_rn(v0, v1);
            *(__half2*)(Ch + pr1 * N + cg) = __floats2half2_rn(v2, v3);
        }
    }

    if (a_s) {
        float sp[2][2] = {{0.f, 0.f}, {0.f, 0.f}};
        float dp[2][2] = {{0.f, 0.f}, {0.f, 0.f}};
#pragma unroll
        for (int mt = 0; mt < 2; mt++)
#pragma unroll
            for (int nt = 0; nt < 8; nt++) {
                const int cl = n0 + nt * 8 + (lane & 3) * 2;
                sp[mt][0] += acc[mt][nt][0] * sas[cl] + acc[mt][nt][1] * sas[cl + 1];
                dp[mt][0] += acc[mt][nt][0] * sad[cl] + acc[mt][nt][1] * sad[cl + 1];
                sp[mt][1] += acc[mt][nt][2] * sas[cl] + acc[mt][nt][3] * sas[cl + 1];
                dp[mt][1] += acc[mt][nt][2] * sad[cl] + acc[mt][nt][3] * sad[cl + 1];
            }
#pragma unroll
        for (int mt = 0; mt < 2; mt++)
#pragma unroll
            for (int h8 = 0; h8 < 2; h8++) {
                float s = sp[mt][h8], d = dp[mt][h8];
                s += __shfl_xor_sync(0xffffffffu, s, 1);
                s += __shfl_xor_sync(0xffffffffu, s, 2);
                d += __shfl_xor_sync(0xffffffffu, d, 1);
                d += __shfl_xor_sync(0xffffffffu, d, 2);
                if ((lane & 3) == 0) {
                    int rw = mt * 16 + h8 * 8 + (lane >> 2);
                    sredS[wid][rw] = s;
                    sredD[wid][rw] = d;
                }
            }
        __syncthreads();
        if (wid < 4) {
            float s = sredS[wid][lane] + sredS[wid + 4][lane];
            float d = sredD[wid][lane] + sredD[wid + 4][lane];
            int n = by * 128 + wid * 32 + lane;
            pas8[n * 8 + bx] = s;
            pad8[n * 8 + bx] = d;
        }
    }
}

// ---------------------------------------------------------------------------
// Alpha helpers
// ---------------------------------------------------------------------------
__device__ __forceinline__ float rd_as(const float* p8, int n, int hd) {
    return p8[n * 8 + 2 * hd] + p8[n * 8 + 2 * hd + 1];
}

// ---------------------------------------------------------------------------
// Strip aggregation (concat layers). h is INTERLEAVED.
// grid = 4096 (region strips of 2 timesteps) + 8192 (audio even/odd pairs).
// ---------------------------------------------------------------------------
__global__ __launch_bounds__(256, 4) void agg_strip_kernel(
    const half_t* __restrict__ h, const float* __restrict__ pas8,
    const float* __restrict__ pad8, const float* __restrict__ bias,
    half_t* __restrict__ outA)
{
    const int bid = blockIdx.x, tid = threadIdx.x;
    if (bid < 4096) {
        const int bt0 = bid * 2;
        const int t0 = bt0 & 511;
        __shared__ float wc[2][4][4][4];
        __shared__ float wp[2][4][4];
        if (tid < 32) {
            int tt = tid >> 4, j = (tid >> 2) & 3, hd = tid & 3;
            int bt = bt0 + tt, t = t0 + tt;
            int n = j * 8192 + bt;
            float adv = rd_as(pad8, n, hd);
            float e[5]; int ei[3]; int cnt = 0;
            for (int i = 0; i < 4; i++)
                if (i != j) { e[cnt] = rd_as(pas8, i * 8192 + bt, hd) + adv; ei[cnt] = i; cnt++; }
            int prevIdx = -1;
            if (t > 0) { e[cnt] = rd_as(pas8, n - 1, hd) + adv; prevIdx = cnt; cnt++; }
            int selfIdx = cnt; e[cnt] = rd_as(pas8, n, hd) + adv; cnt++;
            float m = -1e30f;
            for (int k = 0; k < cnt; k++) { float v = e[k]; v = v >= 0.f ? v : 0.2f * v; e[k] = v; m = fmaxf(m, v); }
            float den = 0.f;
            for (int k = 0; k < cnt; k++) { e[k] = __expf(e[k] - m); den += e[k]; }
            float inv = 1.f / (den + 1e-16f);
            float w4[4] = {0.f, 0.f, 0.f, 0.f};
            for (int k = 0; k < 3; k++) w4[ei[k]] = e[k] * inv;
            w4[j] = e[selfIdx] * inv;
            for (int i = 0; i < 4; i++) wc[tt][j][hd][i] = w4[i];
            wp[tt][j][hd] = (prevIdx >= 0) ? e[prevIdx] * inv : 0.f;
        }
        __syncthreads();
        const int c4 = tid * 4;
        const int hd = c4 >> 8;
        float4 bb = *(const float4*)&bias[c4];
        float4 prv[4];
        if (t0 > 0) {
#pragma unroll
            for (int i = 0; i < 4; i++)
                prv[i] = ld_h4(h + (size_t)((bt0 - 1) * 4 + i) * 1024 + c4);
        } else {
#pragma unroll
            for (int i = 0; i < 4; i++) prv[i] = make_float4(0.f, 0.f, 0.f, 0.f);
        }
#pragma unroll
        for (int tt = 0; tt < 2; tt++) {
            const int bt = bt0 + tt;
            float4 cur[4];
#pragma unroll
            for (int i = 0; i < 4; i++)
                cur[i] = ld_h4(h + (size_t)(bt * 4 + i) * 1024 + c4);
#pragma unroll
            for (int j = 0; j < 4; j++) {
                float w0 = wc[tt][j][hd][0], w1 = wc[tt][j][hd][1];
                float w2 = wc[tt][j][hd][2], w3 = wc[tt][j][hd][3], wpp = wp[tt][j][hd];
                float4 o;
                o.x = w0 * cur[0].x + w1 * cur[1].x + w2 * cur[2].x + w3 * cur[3].x + wpp * prv[j].x + bb.x;
                o.y = w0 * cur[0].y + w1 * cur[1].y + w2 * cur[2].y + w3 * cur[3].y + wpp * prv[j].y + bb.y;
                o.z = w0 * cur[0].z + w1 * cur[1].z + w2 * cur[2].z + w3 * cur[3].z + wpp * prv[j].z + bb.z;
                o.w = w0 * cur[0].w + w1 * cur[1].w + w2 * cur[2].w + w3 * cur[3].w + wpp * prv[j].w + bb.w;
                st_h4(outA, (size_t)(j * 8192 + bt) * 1024 + c4, o);
            }
#pragma unroll
            for (int i = 0; i < 4; i++) prv[i] = cur[i];
        }
    } else {
        const int ap = bid - 4096;
        const int b = ap >> 9, tp = ap & 511;
        const int n0 = 32768 + b * 1024 + 2 * tp;
        const int bt = b * 512 + tp;
        __shared__ float al[4][3];
        if (tid < 4) {
            int hd = tid;
            int srcs[3] = { 8192 + bt, 16384 + bt, n0 };
            float adv = rd_as(pad8, n0, hd);
            float e[3], m = -1e30f;
            for (int k = 0; k < 3; k++) {
                float v = rd_as(pas8, srcs[k], hd) + adv;
                v = v >= 0.f ? v : 0.2f * v;
                e[k] = v; m = fmaxf(m, v);
            }
            float den = 0.f;
            for (int k = 0; k < 3; k++) { e[k] = __expf(e[k] - m); den += e[k]; }
            float inv = 1.f / (den + 1e-16f);
            for (int k = 0; k < 3; k++) al[hd][k] = e[k] * inv;
        }
        __syncthreads();
        const int c4 = tid * 4;
        const int hd = c4 >> 8;
        float4 bb = *(const float4*)&bias[c4];
        float4 vL = ld_h4(h + (size_t)(bt * 4 + 1) * 1024 + c4);
        float4 vR = ld_h4(h + (size_t)(bt * 4 + 2) * 1024 + c4);
        float4 vS = ld_h4(h + (size_t)n0 * 1024 + c4);
        float w0 = al[hd][0], w1 = al[hd][1], w2 = al[hd][2];
        float4 o;
        o.x = w0 * vL.x + w1 * vR.x + w2 * vS.x + bb.x;
        o.y = w0 * vL.y + w1 * vR.y + w2 * vS.y + bb.y;
        o.z = w0 * vL.z + w1 * vR.z + w2 * vS.z + bb.z;
        o.w = w0 * vL.w + w1 * vR.w + w2 * vS.w + bb.w;
        st_h4(outA, (size_t)n0 * 1024 + c4, o);
        float4 vO = ld_h4(h + (size_t)(n0 + 1) * 1024 + c4);
        float4 o2 = make_float4(vO.x + bb.x, vO.y + bb.y, vO.z + bb.z, vO.w + bb.w);
        st_h4(outA, (size_t)(n0 + 1) * 1024 + c4, o2);
    }
}

// ---------------------------------------------------------------------------
// Fused: head-mean aggregation (layer 2) + LayerNorm + per-batch mean partial.
// h is INTERLEAVED.
// ---------------------------------------------------------------------------
__device__ __forceinline__ void ln_atomic_row(
    float o, int tid, int warp, int lane, float (*red)[8],
    const float* ln_g, const float* ln_b, float* part, int b_out)
{
    float s = o, q = o * o;
#pragma unroll
    for (int off = 16; off; off >>= 1) {
        s += __shfl_xor_sync(0xffffffffu, s, off);
        q += __shfl_xor_sync(0xffffffffu, q, off);
    }
    if (lane == 0) { red[0][warp] = s; red[1][warp] = q; }
    __syncthreads();
    float ts = 0.f, tq = 0.f;
#pragma unroll
    for (int w = 0; w < 8; w++) { ts += red[0][w]; tq += red[1][w]; }
    float mu = ts * (1.f / 256.f);
    float var = tq * (1.f / 256.f) - mu * mu;
    float rstd = rsqrtf(var + 1e-5f);
    float v = (o - mu) * rstd * ln_g[tid] + ln_b[tid];
    atomicAdd(&part[b_out * 256 + tid], v);
    __syncthreads();
}

__global__ __launch_bounds__(256, 4) void agg_mean_ln_kernel(
    const half_t* __restrict__ h, const float* __restrict__ pas8,
    const float* __restrict__ pad8, const float* __restrict__ bias,
    const float* __restrict__ ln_g, const float* __restrict__ ln_b,
    float* __restrict__ part)
{
    const int bid = blockIdx.x, tid = threadIdx.x;
    const int warp = tid >> 5, lane = tid & 31;
    __shared__ float red[2][8];
    if (bid < 8192) {
        const int bt = bid, t = bt & 511;
        __shared__ float wcur[4][4][4];
        __shared__ float wprev[4][4];
        if (tid < 16) {
            int j = tid >> 2, hd = tid & 3;
            int n = j * 8192 + bt;
            float adv = rd_as(pad8, n, hd);
            float e[5]; int ei[3]; int cnt = 0;
            for (int i = 0; i < 4; i++)
                if (i != j) { e[cnt] = rd_as(pas8, i * 8192 + bt, hd) + adv; ei[cnt] = i; cnt++; }
            int prevIdx = -1;
            if (t > 0) { e[cnt] = rd_as(pas8, n - 1, hd) + adv; prevIdx = cnt; cnt++; }
            int selfIdx = cnt; e[cnt] = rd_as(pas8, n, hd) + adv; cnt++;
            float m = -1e30f;
            for (int k = 0; k < cnt; k++) { float v = e[k]; v = v >= 0.f ? v : 0.2f * v; e[k] = v; m = fmaxf(m, v); }
            float den = 0.f;
            for (int k = 0; k < cnt; k++) { e[k] = __expf(e[k] - m); den += e[k]; }
            float inv = 1.f / (den + 1e-16f);
            float wcv[4] = {0.f, 0.f, 0.f, 0.f};
            for (int k = 0; k < 3; k++) wcv[ei[k]] = e[k] * inv;
            wcv[j] = e[selfIdx] * inv;
            for (int i = 0; i < 4; i++) wcur[j][hd][i] = wcv[i];
            wprev[j][hd] = (prevIdx >= 0) ? e[prevIdx] * inv : 0.f;
        }
        __syncthreads();
        __shared__ float sm[4][4][256];
        const int hd = tid >> 6, cb = (tid & 63) * 4;
        float4 cur[4], prv[4];
#pragma unroll
        for (int i = 0; i < 4; i++)
            cur[i] = ld_h4(h + (size_t)(bt * 4 + i) * 1024 + hd * 256 + cb);
        if (t > 0) {
#pragma unroll
            for (int i = 0; i < 4; i++)
                prv[i] = ld_h4(h + (size_t)((bt - 1) * 4 + i) * 1024 + hd * 256 + cb);
        } else {
#pragma unroll
            for (int i = 0; i < 4; i++) prv[i] = make_float4(0.f, 0.f, 0.f, 0.f);
        }
#pragma unroll
        for (int j = 0; j < 4; j++) {
            float w0 = wcur[j][hd][0], w1 = wcur[j][hd][1];
            float w2 = wcur[j][hd][2], w3 = wcur[j][hd][3], wpp = wprev[j][hd];
            float4 o;
            o.x = w0 * cur[0].x + w1 * cur[1].x + w2 * cur[2].x + w3 * cur[3].x + wpp * prv[j].x;
            o.y = w0 * cur[0].y + w1 * cur[1].y + w2 * cur[2].y + w3 * cur[3].y + wpp * prv[j].y;
            o.z = w0 * cur[0].z + w1 * cur[1].z + w2 * cur[2].z + w3 * cur[3].z + wpp * prv[j].z;
            o.w = w0 * cur[0].w + w1 * cur[1].w + w2 * cur[2].w + w3 * cur[3].w + wpp * prv[j].w;
            *(float4*)&sm[hd][j][cb] = o;
        }
        __syncthreads();
#pragma unroll
        for (int j = 0; j < 4; j++) {
            float o = (sm[0][j][tid] + sm[1][j][tid] + sm[2][j][tid] + sm[3][j][tid]) * 0.25f
                    + bias[tid];
            int n = j * 8192 + bt;
            ln_atomic_row(o, tid, warp, lane, red, ln_g, ln_b, part, n / 3072);
        }
    } else {
        const int ap = bid - 8192;
        const int b = ap >> 9, tp = ap & 511;
        const int n0 = 32768 + b * 1024 + 2 * tp;
        const int bt = b * 512 + tp;
        __shared__ float al[4][3];
        if (tid < 4) {
            int hd = tid;
            int srcs[3] = { 8192 + bt, 16384 + bt, n0 };
            float adv = rd_as(pad8, n0, hd);
            float e[3], m = -1e30f;
            for (int k = 0; k < 3; k++) {
                float v = rd_as(pas8, srcs[k], hd) + adv;
                v = v >= 0.f ? v : 0.2f * v;
                e[k] = v; m = fmaxf(m, v);
            }
            float den = 0.f;
            for (int k = 0; k < 3; k++) { e[k] = __expf(e[k] - m); den += e[k]; }
            float inv = 1.f / (den + 1e-16f);
            for (int k = 0; k < 3; k++) al[hd][k] = e[k] * inv;
        }
        __syncthreads();
        __shared__ float sm2[2][4][256];
        const int hd = tid >> 6, cb = (tid & 63) * 4;
        {
            float4 vL = ld_h4(h + (size_t)(bt * 4 + 1) * 1024 + hd * 256 + cb);
            float4 vR = ld_h4(h + (size_t)(bt * 4 + 2) * 1024 + hd * 256 + cb);
            float4 vS = ld_h4(h + (size_t)n0 * 1024 + hd * 256 + cb);
            float w0 = al[hd][0], w1 = al[hd][1], w2 = al[hd][2];
            float4 o;
            o.x = w0 * vL.x + w1 * vR.x + w2 * vS.x;
            o.y = w0 * vL.y + w1 * vR.y + w2 * vS.y;
            o.z = w0 * vL.z + w1 * vR.z + w2 * vS.z;
            o.w = w0 * vL.w + w1 * vR.w + w2 * vS.w;
            *(float4*)&sm2[0][hd][cb] = o;
        }
        {
            float4 vO = ld_h4(h + (size_t)(n0 + 1) * 1024 + hd * 256 + cb);
            *(float4*)&sm2[1][hd][cb] = vO;
        }
        __syncthreads();
#pragma unroll
        for (int e = 0; e < 2; e++) {
            float o = (sm2[e][0][tid] + sm2[e][1][tid] + sm2[e][2][tid] + sm2[e][3][tid]) * 0.25f
                    + bias[tid];
            int n = n0 + e;
            ln_atomic_row(o, tid, warp, lane, red, ln_g, ln_b, part, n / 3072);
        }
    }
}

__global__ void reduce_out_kernel(const float* __restrict__ part, float* __restrict__ out)
{
    int b = blockIdx.x, c = threadIdx.x;
    out[b * 256 + c] = part[b * 256 + c] * (1.f / 3072.f);
}

// ---------------------------------------------------------------------------
// Launch
// ---------------------------------------------------------------------------
extern "C" void kernel_launch(void* const* d_in, const int* in_sizes, int n_in,
                              void* d_out, int out_size)
{
    Ptr5 inp = {{ (const float*)d_in[0], (const float*)d_in[1], (const float*)d_in[2],
                  (const float*)d_in[3], (const float*)d_in[4] }};
    Ptr5 wP  = {{ (const float*)d_in[5], (const float*)d_in[7], (const float*)d_in[9],
                  (const float*)d_in[11], (const float*)d_in[13] }};
    Ptr5 projb = {{ (const float*)d_in[6], (const float*)d_in[8], (const float*)d_in[10],
                    (const float*)d_in[12], (const float*)d_in[14] }};
    Ptr5 nob = {{ nullptr, nullptr, nullptr, nullptr, nullptr }};
    const float* W0 = (const float*)d_in[15];
    const float* as0 = (const float*)d_in[16];
    const float* ad0 = (const float*)d_in[17];
    const float* bias0 = (const float*)d_in[18];
    const float* W1 = (const float*)d_in[19];
    const float* as1 = (const float*)d_in[20];
    const float* ad1 = (const float*)d_in[21];
    const float* bias1 = (const float*)d_in[22];
    const float* W2 = (const float*)d_in[23];
    const float* as2 = (const float*)d_in[24];
    const float* ad2 = (const float*)d_in[25];
    const float* bias2 = (const float*)d_in[26];
    const float* ln_g = (const float*)d_in[27];
    const float* ln_b = (const float*)d_in[28];
    float* out = (float*)d_out;

    float *pas8, *pad8, *part;
    half_t *hh, *a0, *a1, *wh;
    cudaGetSymbolAddress((void**)&hh, g_hh);
    cudaGetSymbolAddress((void**)&pas8, g_pas8);
    cudaGetSymbolAddress((void**)&pad8, g_pad8);
    cudaGetSymbolAddress((void**)&part, g_part);
    cudaGetSymbolAddress((void**)&a0, g_a0);
    cudaGetSymbolAddress((void**)&a1, g_a1);
    cudaGetSymbolAddress((void**)&wh, g_wh);

    cudaFuncSetAttribute(mma_gemm_t<0>, cudaFuncAttributeMaxDynamicSharedMemorySize, GEMM_DSMEM);
    cudaFuncSetAttribute(mma_gemm_t<1>, cudaFuncAttributeMaxDynamicSharedMemorySize, GEMM_DSMEM);

    const size_t OFF_PROJ = 0;
    const size_t OFF_W0 = 5 * 131072;
    const size_t OFF_W1 = OFF_W0 + 262144;
    const size_t OFF_W2 = OFF_W1 + 1048576;

    // launch 0: weight prep + part zeroing
    prep_w_kernel<<<2945, 256>>>(wP, W0, W1, W2, wh, part);

    // launch 1: projections (fp32 A fused convert, batched 5 segments) -> a1
    mma_gemm_t<1><<<dim3(2, 384), 256, GEMM_DSMEM>>>(
        nullptr, inp, wh + OFF_PROJ, 131072, 5, projb, /*permC=*/0,
        a1, nullptr, nullptr, nullptr, nullptr,
        NNODES, 256, 512);

    // launch 2: GAT layer 0 GEMM (K=256) -> h interleaved
    mma_gemm_t<0><<<dim3(8, 384), 256, GEMM_DSMEM>>>(
        a1, nob, wh + OFF_W0, 0, 1, nob, /*permC=*/1,
        hh, as0, ad0, pas8, pad8,
        NNODES, 1024, 256);
    // launch 3: aggregate 0
    agg_strip_kernel<<<12288, 256>>>(hh, pas8, pad8, bias0, a0);

    // launch 4: GAT layer 1 GEMM (K=1024) -> h interleaved
    mma_gemm_t<0><<<dim3(8, 384), 256, GEMM_DSMEM>>>(
        a0, nob, wh + OFF_W1, 0, 1, nob, /*permC=*/1,
        hh, as1, ad1, pas8, pad8,
        NNODES, 1024, 1024);
    // launch 5: aggregate 1
    agg_strip_kernel<<<12288, 256>>>(hh, pas8, pad8, bias1, a1);

    // launch 6: GAT layer 2 GEMM (K=1024) -> h interleaved
    mma_gemm_t<0><<<dim3(8, 384), 256, GEMM_DSMEM>>>(
        a1, nob, wh + OFF_W2, 0, 1, nob, /*permC=*/1,
        hh, as2, ad2, pas8, pad8,
        NNODES, 1024, 1024);
    // launch 7: fused head-mean aggregate + LayerNorm + batch-mean partials
    agg_mean_ln_kernel<<<16384, 256>>>(hh, pas8, pad8, bias2, ln_g, ln_b, part);

    // launch 8: final scale
    reduce_out_kernel<<<16, 256>>>(part, out);
}